// round 1
// baseline (speedup 1.0000x reference)
#include <cuda_runtime.h>
#include <cuda_bf16.h>

// Problem constants
#define BATCH 8
#define SEQ   2048
#define EMB   1024
#define HD    64
#define MROWS (BATCH*SEQ)      // 16384
#define SCALE 0.03125f          // 1024^-0.5

// Scratch for q,k,v projections (device globals: no allocation allowed)
__device__ float g_q[MROWS*HD];
__device__ float g_k[MROWS*HD];
__device__ float g_v[MROWS*HD];

// ---------------------------------------------------------------------------
// Kernel 1: QKV projection. grid = (MROWS/64, 3), block = 256.
// C[64x64] tile, K=1024 in BK=16 steps, 4x4 microtile per thread.
// ---------------------------------------------------------------------------
__global__ __launch_bounds__(256) void qkv_kernel(
    const float* __restrict__ x,
    const float* __restrict__ Wq,
    const float* __restrict__ Wk,
    const float* __restrict__ Wv)
{
    __shared__ float a[16][64];   // [k][row]  (x tile, transposed)
    __shared__ float b[16][64];   // [k][col]  (W tile)

    const float* W  = (blockIdx.y == 0) ? Wq : (blockIdx.y == 1) ? Wk : Wv;
    float*       out = (blockIdx.y == 0) ? g_q : (blockIdx.y == 1) ? g_k : g_v;

    const int row0 = blockIdx.x * 64;
    const int tid  = threadIdx.x;
    const int ty   = tid >> 4;        // 0..15 -> rows ty*4..+3
    const int tx   = tid & 15;        // 0..15 -> cols tx*4..+3

    // A loader: 256 threads load 64x16 floats (one float4 each)
    const int lr = tid >> 2;          // row 0..63
    const int lk = (tid & 3) * 4;     // k offset 0,4,8,12
    // B loader: 256 threads load 16x64 floats (one float4 each)
    const int wk = tid >> 4;          // k 0..15
    const int wc = (tid & 15) * 4;    // col

    float acc[4][4] = {};

    for (int k0 = 0; k0 < EMB; k0 += 16) {
        float4 av = *(const float4*)&x[(size_t)(row0 + lr) * EMB + k0 + lk];
        float4 bv = *(const float4*)&W[(size_t)(k0 + wk) * HD + wc];
        __syncthreads();
        a[lk + 0][lr] = av.x;
        a[lk + 1][lr] = av.y;
        a[lk + 2][lr] = av.z;
        a[lk + 3][lr] = av.w;
        *(float4*)&b[wk][wc] = bv;
        __syncthreads();

#pragma unroll
        for (int kk = 0; kk < 16; kk++) {
            float4 aq = *(const float4*)&a[kk][ty * 4];
            float4 bq = *(const float4*)&b[kk][tx * 4];
            float qa[4] = {aq.x, aq.y, aq.z, aq.w};
            float qb[4] = {bq.x, bq.y, bq.z, bq.w};
#pragma unroll
            for (int i = 0; i < 4; i++)
#pragma unroll
                for (int j = 0; j < 4; j++)
                    acc[i][j] = fmaf(qa[i], qb[j], acc[i][j]);
        }
    }

#pragma unroll
    for (int i = 0; i < 4; i++) {
        float4 o = make_float4(acc[i][0], acc[i][1], acc[i][2], acc[i][3]);
        *(float4*)&out[(size_t)(row0 + ty * 4 + i) * HD + tx * 4] = o;
    }
}

// ---------------------------------------------------------------------------
// Kernel 2: causal flash attention. grid = 256 (batch x 32 q-tiles), block 256.
// q-tile = 64 queries, k-tile = 64 keys. Online softmax. Dynamic smem ~70KB.
// ---------------------------------------------------------------------------
#define ATTN_SMEM_FLOATS (4*4096 + 1024 + 192)
#define ATTN_SMEM_BYTES  (ATTN_SMEM_FLOATS * 4)

__global__ __launch_bounds__(256) void attn_kernel(float* __restrict__ out)
{
    extern __shared__ float sm[];
    float* Qt   = sm;              // [d][q] 64x64
    float* Kt   = Qt + 4096;       // [d][k] 64x64
    float* Vs   = Kt + 4096;       // [k][d] 64x64
    float* Ps   = Vs + 4096;       // [q][k] 64x64
    float* red  = Ps + 4096;       // [64][16] partial max / sum
    float* mrow = red + 1024;      // [64]
    float* lrow = mrow + 64;       // [64]
    float* crow = lrow + 64;       // [64]

    const int bid   = blockIdx.x;
    const int batch = bid & 7;
    const int qt    = 31 - (bid >> 3);   // heavy q-tiles scheduled first
    const int q0    = qt * 64;

    const int tid = threadIdx.x;
    const int ty  = tid >> 4;
    const int tx  = tid & 15;

    const float* qb = g_q + (size_t)batch * SEQ * HD;
    const float* kb = g_k + (size_t)batch * SEQ * HD;
    const float* vb = g_v + (size_t)batch * SEQ * HD;

    // Load Q tile transposed: Qt[d][q]
    {
        const int r  = tid >> 2;          // 0..63 (query row within tile)
        const int c4 = (tid & 3) * 16;    // starting d
#pragma unroll
        for (int i = 0; i < 4; i++) {
            float4 v = *(const float4*)&qb[(size_t)(q0 + r) * HD + c4 + i * 4];
            Qt[(c4 + i * 4 + 0) * 64 + r] = v.x;
            Qt[(c4 + i * 4 + 1) * 64 + r] = v.y;
            Qt[(c4 + i * 4 + 2) * 64 + r] = v.z;
            Qt[(c4 + i * 4 + 3) * 64 + r] = v.w;
        }
        if (tid < 64) { mrow[tid] = -1e30f; lrow[tid] = 0.f; }
    }
    float acc[4][4] = {};
    __syncthreads();

    for (int kt = 0; kt <= qt; kt++) {
        const int k0 = kt * 64;
        // Load K (transposed) and V (direct)
        {
            const int r  = tid >> 2;
            const int c4 = (tid & 3) * 16;
#pragma unroll
            for (int i = 0; i < 4; i++) {
                float4 v = *(const float4*)&kb[(size_t)(k0 + r) * HD + c4 + i * 4];
                Kt[(c4 + i * 4 + 0) * 64 + r] = v.x;
                Kt[(c4 + i * 4 + 1) * 64 + r] = v.y;
                Kt[(c4 + i * 4 + 2) * 64 + r] = v.z;
                Kt[(c4 + i * 4 + 3) * 64 + r] = v.w;
                float4 w = *(const float4*)&vb[(size_t)(k0 + r) * HD + c4 + i * 4];
                *(float4*)&Vs[r * 64 + c4 + i * 4] = w;
            }
        }
        __syncthreads();

        // S = Q K^T  (4x4 microtile per thread)
        float s[4][4] = {};
#pragma unroll
        for (int d = 0; d < 64; d++) {
            float4 qv = *(const float4*)&Qt[d * 64 + ty * 4];
            float4 kv = *(const float4*)&Kt[d * 64 + tx * 4];
            float qa[4] = {qv.x, qv.y, qv.z, qv.w};
            float ka[4] = {kv.x, kv.y, kv.z, kv.w};
#pragma unroll
            for (int i = 0; i < 4; i++)
#pragma unroll
                for (int j = 0; j < 4; j++)
                    s[i][j] = fmaf(qa[i], ka[j], s[i][j]);
        }
        // scale + causal mask (only diagonal tile needs masking)
#pragma unroll
        for (int i = 0; i < 4; i++) {
            const int qrow = q0 + ty * 4 + i;
#pragma unroll
            for (int j = 0; j < 4; j++) {
                s[i][j] *= SCALE;
                if (kt == qt && (k0 + tx * 4 + j) > qrow) s[i][j] = -1e30f;
            }
        }
        // per-thread partial row max
#pragma unroll
        for (int i = 0; i < 4; i++) {
            float pm = fmaxf(fmaxf(s[i][0], s[i][1]), fmaxf(s[i][2], s[i][3]));
            red[(ty * 4 + i) * 16 + tx] = pm;
        }
        __syncthreads();

        if (tid < 64) {
            float m_old = mrow[tid];
            float mx = m_old;
#pragma unroll
            for (int j = 0; j < 16; j++) mx = fmaxf(mx, red[tid * 16 + j]);
            crow[tid] = __expf(m_old - mx);
            mrow[tid] = mx;
        }
        __syncthreads();

        // P = exp(S - m), store + partial row sums; rescale accumulators
#pragma unroll
        for (int i = 0; i < 4; i++) {
            const int qr = ty * 4 + i;
            const float nm = mrow[qr];
            float p0 = __expf(s[i][0] - nm);
            float p1 = __expf(s[i][1] - nm);
            float p2 = __expf(s[i][2] - nm);
            float p3 = __expf(s[i][3] - nm);
            *(float4*)&Ps[qr * 64 + tx * 4] = make_float4(p0, p1, p2, p3);
            red[qr * 16 + tx] = p0 + p1 + p2 + p3;
            const float c = crow[qr];
            acc[i][0] *= c; acc[i][1] *= c; acc[i][2] *= c; acc[i][3] *= c;
        }
        __syncthreads();

        if (tid < 64) {
            float sum = 0.f;
#pragma unroll
            for (int j = 0; j < 16; j++) sum += red[tid * 16 + j];
            lrow[tid] = lrow[tid] * crow[tid] + sum;
        }

        // O += P V
#pragma unroll
        for (int k = 0; k < 64; k++) {
            float4 vv = *(const float4*)&Vs[k * 64 + tx * 4];
            float va[4] = {vv.x, vv.y, vv.z, vv.w};
            float p0 = Ps[(ty * 4 + 0) * 64 + k];
            float p1 = Ps[(ty * 4 + 1) * 64 + k];
            float p2 = Ps[(ty * 4 + 2) * 64 + k];
            float p3 = Ps[(ty * 4 + 3) * 64 + k];
            float pa[4] = {p0, p1, p2, p3};
#pragma unroll
            for (int i = 0; i < 4; i++)
#pragma unroll
                for (int j = 0; j < 4; j++)
                    acc[i][j] = fmaf(pa[i], va[j], acc[i][j]);
        }
        __syncthreads();
    }

    // Epilogue: divide by l, write out
#pragma unroll
    for (int i = 0; i < 4; i++) {
        const int qr = ty * 4 + i;
        const float inv = 1.f / lrow[qr];
        float4 o = make_float4(acc[i][0] * inv, acc[i][1] * inv,
                               acc[i][2] * inv, acc[i][3] * inv);
        *(float4*)&out[(size_t)batch * SEQ * HD + (size_t)(q0 + qr) * HD + tx * 4] = o;
    }
}

// ---------------------------------------------------------------------------
extern "C" void kernel_launch(void* const* d_in, const int* in_sizes, int n_in,
                              void* d_out, int out_size)
{
    const float* x  = (const float*)d_in[0];
    const float* Wq = (const float*)d_in[1];
    const float* Wk = (const float*)d_in[2];
    const float* Wv = (const float*)d_in[3];
    float* out = (float*)d_out;

    static bool attr_set = false;
    if (!attr_set) {
        cudaFuncSetAttribute(attn_kernel,
                             cudaFuncAttributeMaxDynamicSharedMemorySize,
                             ATTN_SMEM_BYTES);
        attr_set = true;
    }

    dim3 g1(MROWS / 64, 3);
    qkv_kernel<<<g1, 256>>>(x, Wq, Wk, Wv);

    attn_kernel<<<BATCH * 32, 256, ATTN_SMEM_BYTES>>>(out);
}

// round 3
// speedup vs baseline: 1.0442x; 1.0442x over previous
#include <cuda_runtime.h>
#include <cuda_bf16.h>
#include <cstdint>

// Problem constants
#define BATCH 8
#define SEQ   2048
#define EMB   1024
#define HD    64
#define MROWS (BATCH*SEQ)      // 16384
#define SCALE 0.03125f         // 1024^-0.5

// Scratch (device globals: no allocation allowed)
__device__ float g_q[MROWS*HD];
__device__ float g_k[MROWS*HD];
__device__ float g_v[MROWS*HD];

// ---------------------------------------------------------------------------
// f32x2 packed-math helpers (FFMA2: 2 fp32 FMA per instruction, sm_100+ base)
// ---------------------------------------------------------------------------
typedef unsigned long long u64;

__device__ __forceinline__ u64 pk2(float v) {
    u64 r;
    asm("mov.b64 %0, {%1, %1};" : "=l"(r) : "f"(v));
    return r;
}
__device__ __forceinline__ void fma2(u64& d, u64 a, u64 b) {
    asm("fma.rn.f32x2 %0, %1, %2, %3;" : "=l"(d) : "l"(a), "l"(b), "l"(d));
}
__device__ __forceinline__ void mul2(u64& d, u64 a, u64 b) {
    asm("mul.rn.f32x2 %0, %1, %2;" : "=l"(d) : "l"(a), "l"(b));
}
__device__ __forceinline__ float2 up2(u64 v) {
    float2 f;
    asm("mov.b64 {%0, %1}, %2;" : "=f"(f.x), "=f"(f.y) : "l"(v));
    return f;
}

// ---------------------------------------------------------------------------
// Kernel 1: QKV projection. grid = (MROWS/128, 3), block = 128.
// C[128x64] tile, BK=16, 8x8 microtile per thread, f32x2 math.
// ---------------------------------------------------------------------------
__global__ __launch_bounds__(128) void qkv_kernel(
    const float* __restrict__ x,
    const float* __restrict__ Wq,
    const float* __restrict__ Wk,
    const float* __restrict__ Wv)
{
    __shared__ float a[16][128];   // [k][m]
    __shared__ float b[16][72];    // [k][n] (stride 72 keeps 16B align)

    const float* W  = (blockIdx.y == 0) ? Wq : (blockIdx.y == 1) ? Wk : Wv;
    float*      out = (blockIdx.y == 0) ? g_q : (blockIdx.y == 1) ? g_k : g_v;

    const int row0 = blockIdx.x * 128;
    const int tid  = threadIdx.x;
    const int ty   = tid >> 3;       // 0..15 -> rows ty*8..+7
    const int tx   = tid & 7;        // 0..7  -> cols tx*8..+7

    u64 acc2[8][4] = {};             // 8 rows x 4 col-pairs (fp32 pairs)

    for (int k0 = 0; k0 < EMB; k0 += 16) {
        // stage loads in registers
        float4 av[4];
#pragma unroll
        for (int j = 0; j < 4; j++)
            av[j] = *(const float4*)&x[(size_t)(row0 + tid) * EMB + k0 + j * 4];
        float4 bv[2];
        int bk[2], bn[2];
#pragma unroll
        for (int j = 0; j < 2; j++) {
            int idx = tid * 2 + j;           // 0..255
            bk[j] = idx >> 4;                // 0..15
            bn[j] = (idx & 15) * 4;          // 0..60
            bv[j] = *(const float4*)&W[(size_t)(k0 + bk[j]) * HD + bn[j]];
        }
        __syncthreads();
#pragma unroll
        for (int j = 0; j < 4; j++) {
            a[j * 4 + 0][tid] = av[j].x;
            a[j * 4 + 1][tid] = av[j].y;
            a[j * 4 + 2][tid] = av[j].z;
            a[j * 4 + 3][tid] = av[j].w;
        }
#pragma unroll
        for (int j = 0; j < 2; j++)
            *(float4*)&b[bk[j]][bn[j]] = bv[j];
        __syncthreads();

#pragma unroll
        for (int kk = 0; kk < 16; kk++) {
            float4 a0 = *(const float4*)&a[kk][ty * 8];
            float4 a1 = *(const float4*)&a[kk][ty * 8 + 4];
            ulonglong2 b0 = *(const ulonglong2*)&b[kk][tx * 8];
            ulonglong2 b1 = *(const ulonglong2*)&b[kk][tx * 8 + 4];
            float aa[8] = {a0.x, a0.y, a0.z, a0.w, a1.x, a1.y, a1.z, a1.w};
#pragma unroll
            for (int i = 0; i < 8; i++) {
                u64 ad = pk2(aa[i]);
                fma2(acc2[i][0], ad, b0.x);
                fma2(acc2[i][1], ad, b0.y);
                fma2(acc2[i][2], ad, b1.x);
                fma2(acc2[i][3], ad, b1.y);
            }
        }
    }

#pragma unroll
    for (int i = 0; i < 8; i++) {
        float2 p0 = up2(acc2[i][0]), p1 = up2(acc2[i][1]);
        float2 p2 = up2(acc2[i][2]), p3 = up2(acc2[i][3]);
        float* dst = out + (size_t)(row0 + ty * 8 + i) * HD + tx * 8;
        *(float4*)dst       = make_float4(p0.x, p0.y, p1.x, p1.y);
        *(float4*)(dst + 4) = make_float4(p2.x, p2.y, p3.x, p3.y);
    }
}

// ---------------------------------------------------------------------------
// Kernel 2: causal flash attention, 128 threads, 64x64 tiles, 8x4 microtile,
// f32x2 math. grid = 256 (batch x 32 q-tiles, heavy first).
// ---------------------------------------------------------------------------
#define PSTR 68
#define RSTR 17
#define ATTN_SMEM_FLOATS (4096*3 + 64*PSTR + 64*RSTR + 192)
#define ATTN_SMEM_BYTES  (ATTN_SMEM_FLOATS * 4)

__global__ __launch_bounds__(128) void attn_kernel(float* __restrict__ out)
{
    extern __shared__ float smf[];
    float* Qt   = smf;                 // [d][q] 64x64
    float* Kt   = Qt + 4096;           // [d][k] 64x64
    float* Vs   = Kt + 4096;           // [k][d] 64x64
    float* Ps   = Vs + 4096;           // [q][PSTR]
    float* red  = Ps + 64 * PSTR;      // [q][RSTR]
    float* mrow = red + 64 * RSTR;     // [64]
    float* lrow = mrow + 64;
    float* crow = lrow + 64;

    const int bid   = blockIdx.x;
    const int batch = bid & 7;
    const int qt    = 31 - (bid >> 3);   // heavy q-tiles first
    const int q0    = qt * 64;

    const int tid = threadIdx.x;
    const int ty  = tid >> 4;         // 0..7  -> rows ty*8..+7
    const int tx  = tid & 15;         // 0..15 -> cols tx*4..+3

    const float* qb = g_q + (size_t)batch * SEQ * HD;
    const float* kb = g_k + (size_t)batch * SEQ * HD;
    const float* vb = g_v + (size_t)batch * SEQ * HD;

    // Load Q transposed: each thread covers half a query row (32 d)
    const int lr  = tid >> 1;          // 0..63
    const int ld0 = (tid & 1) * 32;    // 0 or 32
    {
#pragma unroll
        for (int i = 0; i < 8; i++) {
            float4 v = *(const float4*)&qb[(size_t)(q0 + lr) * HD + ld0 + i * 4];
            Qt[(ld0 + i * 4 + 0) * 64 + lr] = v.x;
            Qt[(ld0 + i * 4 + 1) * 64 + lr] = v.y;
            Qt[(ld0 + i * 4 + 2) * 64 + lr] = v.z;
            Qt[(ld0 + i * 4 + 3) * 64 + lr] = v.w;
        }
        if (tid < 64) { mrow[tid] = -1e30f; lrow[tid] = 0.f; }
    }
    u64 acc2[8][2] = {};               // 8 rows x 2 d-col pairs
    __syncthreads();

    for (int kt = 0; kt <= qt; kt++) {
        const int k0 = kt * 64;

        // stage K/V loads (overlap with prev-iter smem reads)
        float4 kreg[8], vreg[8];
#pragma unroll
        for (int i = 0; i < 8; i++) {
            kreg[i] = *(const float4*)&kb[(size_t)(k0 + lr) * HD + ld0 + i * 4];
            vreg[i] = *(const float4*)&vb[(size_t)(k0 + lr) * HD + ld0 + i * 4];
        }
        __syncthreads();   // prev iter S/PV smem reads done
#pragma unroll
        for (int i = 0; i < 8; i++) {
            Kt[(ld0 + i * 4 + 0) * 64 + lr] = kreg[i].x;
            Kt[(ld0 + i * 4 + 1) * 64 + lr] = kreg[i].y;
            Kt[(ld0 + i * 4 + 2) * 64 + lr] = kreg[i].z;
            Kt[(ld0 + i * 4 + 3) * 64 + lr] = kreg[i].w;
            *(float4*)&Vs[lr * 64 + ld0 + i * 4] = vreg[i];
        }
        __syncthreads();

        // S = Q K^T  (8x4 microtile, f32x2)
        u64 s2[8][2] = {};
#pragma unroll
        for (int d = 0; d < 64; d++) {
            float4 qv0 = *(const float4*)&Qt[d * 64 + ty * 8];
            float4 qv1 = *(const float4*)&Qt[d * 64 + ty * 8 + 4];
            ulonglong2 kp = *(const ulonglong2*)&Kt[d * 64 + tx * 4];
            float qa[8] = {qv0.x, qv0.y, qv0.z, qv0.w, qv1.x, qv1.y, qv1.z, qv1.w};
#pragma unroll
            for (int i = 0; i < 8; i++) {
                u64 ad = pk2(qa[i]);
                fma2(s2[i][0], ad, kp.x);
                fma2(s2[i][1], ad, kp.y);
            }
        }
        // unpack, scale + causal mask (diagonal tile only)
        float s[8][4];
#pragma unroll
        for (int i = 0; i < 8; i++) {
            float2 u0 = up2(s2[i][0]);
            float2 u1 = up2(s2[i][1]);
            s[i][0] = u0.x; s[i][1] = u0.y; s[i][2] = u1.x; s[i][3] = u1.y;
            const int qrow = q0 + ty * 8 + i;
#pragma unroll
            for (int j = 0; j < 4; j++) {
                s[i][j] *= SCALE;
                if (kt == qt && (k0 + tx * 4 + j) > qrow) s[i][j] = -1e30f;
            }
        }
        // per-thread partial row max
#pragma unroll
        for (int i = 0; i < 8; i++) {
            float pm = fmaxf(fmaxf(s[i][0], s[i][1]), fmaxf(s[i][2], s[i][3]));
            red[(ty * 8 + i) * RSTR + tx] = pm;
        }
        __syncthreads();

        if (tid < 64) {
            float m_old = mrow[tid];
            float mx = m_old;
#pragma unroll
            for (int j = 0; j < 16; j++) mx = fmaxf(mx, red[tid * RSTR + j]);
            crow[tid] = __expf(m_old - mx);
            mrow[tid] = mx;
        }
        __syncthreads();

        // P = exp(S - m); partial sums; rescale accumulators
#pragma unroll
        for (int i = 0; i < 8; i++) {
            const int qr = ty * 8 + i;
            const float nm = mrow[qr];
            float p0 = __expf(s[i][0] - nm);
            float p1 = __expf(s[i][1] - nm);
            float p2 = __expf(s[i][2] - nm);
            float p3 = __expf(s[i][3] - nm);
            *(float4*)&Ps[qr * PSTR + tx * 4] = make_float4(p0, p1, p2, p3);
            red[qr * RSTR + tx] = p0 + p1 + p2 + p3;
            u64 cc = pk2(crow[qr]);
            mul2(acc2[i][0], acc2[i][0], cc);
            mul2(acc2[i][1], acc2[i][1], cc);
        }
        __syncthreads();

        if (tid < 64) {
            float sum = 0.f;
#pragma unroll
            for (int j = 0; j < 16; j++) sum += red[tid * RSTR + j];
            lrow[tid] = lrow[tid] * crow[tid] + sum;
        }

        // O += P V   (f32x2, 4 k per step)
#pragma unroll
        for (int k4 = 0; k4 < 64; k4 += 4) {
            float4 p[8];
#pragma unroll
            for (int i = 0; i < 8; i++)
                p[i] = *(const float4*)&Ps[(ty * 8 + i) * PSTR + k4];
#pragma unroll
            for (int j = 0; j < 4; j++) {
                ulonglong2 vp = *(const ulonglong2*)&Vs[(k4 + j) * 64 + tx * 4];
#pragma unroll
                for (int i = 0; i < 8; i++) {
                    float pij = (j == 0) ? p[i].x : (j == 1) ? p[i].y
                              : (j == 2) ? p[i].z : p[i].w;
                    u64 pd = pk2(pij);
                    fma2(acc2[i][0], pd, vp.x);
                    fma2(acc2[i][1], pd, vp.y);
                }
            }
        }
    }
    __syncthreads();   // lrow final visible

    // Epilogue
#pragma unroll
    for (int i = 0; i < 8; i++) {
        const int qr = ty * 8 + i;
        const float inv = 1.f / lrow[qr];
        float2 o0 = up2(acc2[i][0]);
        float2 o1 = up2(acc2[i][1]);
        float4 o = make_float4(o0.x * inv, o0.y * inv, o1.x * inv, o1.y * inv);
        *(float4*)&out[(size_t)batch * SEQ * HD + (size_t)(q0 + qr) * HD + tx * 4] = o;
    }
}

// ---------------------------------------------------------------------------
extern "C" void kernel_launch(void* const* d_in, const int* in_sizes, int n_in,
                              void* d_out, int out_size)
{
    const float* x  = (const float*)d_in[0];
    const float* Wq = (const float*)d_in[1];
    const float* Wk = (const float*)d_in[2];
    const float* Wv = (const float*)d_in[3];
    float* out = (float*)d_out;

    static bool attr_set = false;
    if (!attr_set) {
        cudaFuncSetAttribute(attn_kernel,
                             cudaFuncAttributeMaxDynamicSharedMemorySize,
                             ATTN_SMEM_BYTES);
        attr_set = true;
    }

    dim3 g1(MROWS / 128, 3);
    qkv_kernel<<<g1, 128>>>(x, Wq, Wk, Wv);

    attn_kernel<<<BATCH * 32, 128, ATTN_SMEM_BYTES>>>(out);
}

// round 4
// speedup vs baseline: 1.0531x; 1.0085x over previous
#include <cuda_runtime.h>
#include <cuda_bf16.h>
#include <cstdint>

// Problem constants
#define BATCH 8
#define SEQ   2048
#define EMB   1024
#define HD    64
#define MROWS (BATCH*SEQ)      // 16384
#define SCALE 0.03125f         // 1024^-0.5

// Scratch (device globals: no allocation allowed)
__device__ float g_q[MROWS*HD];
__device__ float g_k[MROWS*HD];
__device__ float g_v[MROWS*HD];

// ---------------------------------------------------------------------------
// f32x2 packed-math helpers
// ---------------------------------------------------------------------------
typedef unsigned long long u64;

__device__ __forceinline__ u64 pk2(float v) {
    u64 r;
    asm("mov.b64 %0, {%1, %1};" : "=l"(r) : "f"(v));
    return r;
}
__device__ __forceinline__ void fma2(u64& d, u64 a, u64 b) {
    asm("fma.rn.f32x2 %0, %1, %2, %3;" : "=l"(d) : "l"(a), "l"(b), "l"(d));
}
__device__ __forceinline__ void mul2(u64& d, u64 a, u64 b) {
    asm("mul.rn.f32x2 %0, %1, %2;" : "=l"(d) : "l"(a), "l"(b));
}
__device__ __forceinline__ float2 up2(u64 v) {
    float2 f;
    asm("mov.b64 {%0, %1}, %2;" : "=f"(f.x), "=f"(f.y) : "l"(v));
    return f;
}

// ---------------------------------------------------------------------------
// Kernel 1: QKV projection. grid = (MROWS/128, 3), block = 128.
// C[128x64] tile, BK=16, 8x8 microtile, f32x2, double-buffered (1 sync/iter).
// ---------------------------------------------------------------------------
__global__ __launch_bounds__(128) void qkv_kernel(
    const float* __restrict__ x,
    const float* __restrict__ Wq,
    const float* __restrict__ Wk,
    const float* __restrict__ Wv)
{
    __shared__ float a[2][16][128];   // [buf][k][m]
    __shared__ float b[2][16][72];    // [buf][k][n]

    const float* W  = (blockIdx.y == 0) ? Wq : (blockIdx.y == 1) ? Wk : Wv;
    float*      out = (blockIdx.y == 0) ? g_q : (blockIdx.y == 1) ? g_k : g_v;

    const int row0 = blockIdx.x * 128;
    const int tid  = threadIdx.x;
    const int ty   = tid >> 3;       // 0..15 -> rows ty*8..+7
    const int tx   = tid & 7;        // 0..7  -> cols tx*8..+7

    // b loader indices (2 float4 per thread over 16x64)
    const int bk0 = (tid * 2) >> 4;
    const int bn0 = ((tid * 2) & 15) * 4;
    const int bk1 = (tid * 2 + 1) >> 4;
    const int bn1 = ((tid * 2 + 1) & 15) * 4;

    u64 acc2[8][4] = {};

    // prologue: stage + store chunk 0 into buf0
    float4 av[4], bv0, bv1;
#pragma unroll
    for (int j = 0; j < 4; j++)
        av[j] = *(const float4*)&x[(size_t)(row0 + tid) * EMB + j * 4];
    bv0 = *(const float4*)&W[(size_t)bk0 * HD + bn0];
    bv1 = *(const float4*)&W[(size_t)bk1 * HD + bn1];
#pragma unroll
    for (int j = 0; j < 4; j++) {
        a[0][j * 4 + 0][tid] = av[j].x;
        a[0][j * 4 + 1][tid] = av[j].y;
        a[0][j * 4 + 2][tid] = av[j].z;
        a[0][j * 4 + 3][tid] = av[j].w;
    }
    *(float4*)&b[0][bk0][bn0] = bv0;
    *(float4*)&b[0][bk1][bn1] = bv1;

    for (int c = 0; c < 64; c++) {
        const int cur = c & 1;
        if (c < 63) {
            const int k0 = (c + 1) * 16;
#pragma unroll
            for (int j = 0; j < 4; j++)
                av[j] = *(const float4*)&x[(size_t)(row0 + tid) * EMB + k0 + j * 4];
            bv0 = *(const float4*)&W[(size_t)(k0 + bk0) * HD + bn0];
            bv1 = *(const float4*)&W[(size_t)(k0 + bk1) * HD + bn1];
        }
        __syncthreads();   // buf[cur] visible; prior reads of buf[cur^1] done
        if (c < 63) {
            const int nb = cur ^ 1;
#pragma unroll
            for (int j = 0; j < 4; j++) {
                a[nb][j * 4 + 0][tid] = av[j].x;
                a[nb][j * 4 + 1][tid] = av[j].y;
                a[nb][j * 4 + 2][tid] = av[j].z;
                a[nb][j * 4 + 3][tid] = av[j].w;
            }
            *(float4*)&b[nb][bk0][bn0] = bv0;
            *(float4*)&b[nb][bk1][bn1] = bv1;
        }

#pragma unroll
        for (int kk = 0; kk < 16; kk++) {
            float4 a0 = *(const float4*)&a[cur][kk][ty * 8];
            float4 a1 = *(const float4*)&a[cur][kk][ty * 8 + 4];
            ulonglong2 b0 = *(const ulonglong2*)&b[cur][kk][tx * 8];
            ulonglong2 b1 = *(const ulonglong2*)&b[cur][kk][tx * 8 + 4];
            float aa[8] = {a0.x, a0.y, a0.z, a0.w, a1.x, a1.y, a1.z, a1.w};
#pragma unroll
            for (int i = 0; i < 8; i++) {
                u64 ad = pk2(aa[i]);
                fma2(acc2[i][0], ad, b0.x);
                fma2(acc2[i][1], ad, b0.y);
                fma2(acc2[i][2], ad, b1.x);
                fma2(acc2[i][3], ad, b1.y);
            }
        }
    }

#pragma unroll
    for (int i = 0; i < 8; i++) {
        float2 p0 = up2(acc2[i][0]), p1 = up2(acc2[i][1]);
        float2 p2 = up2(acc2[i][2]), p3 = up2(acc2[i][3]);
        float* dst = out + (size_t)(row0 + ty * 8 + i) * HD + tx * 8;
        *(float4*)dst       = make_float4(p0.x, p0.y, p1.x, p1.y);
        *(float4*)(dst + 4) = make_float4(p2.x, p2.y, p3.x, p3.y);
    }
}

// ---------------------------------------------------------------------------
// Kernel 2: causal flash attention.
// 256 threads, 64x64 tiles, 4x4 microtile, register softmax via shfl,
// 3 syncs per tile-step, f32x2. grid = 256 (batch x 32 q-tiles, heavy first).
// ---------------------------------------------------------------------------
#define VSTR 68
#define PSTR 68
#define ATTN_SMEM_FLOATS (4096*2 + 64*VSTR + 64*PSTR)
#define ATTN_SMEM_BYTES  (ATTN_SMEM_FLOATS * 4)

__global__ __launch_bounds__(256) void attn_kernel(float* __restrict__ out)
{
    extern __shared__ float smf[];
    float* Qt = smf;              // [d][q] 64x64 (pre-scaled by SCALE)
    float* Kt = Qt + 4096;        // [d][k] 64x64
    float* Vs = Kt + 4096;        // [k][VSTR]
    float* Ps = Vs + 64 * VSTR;   // [q][PSTR]

    const int bid   = blockIdx.x;
    const int batch = bid & 7;
    const int qt    = 31 - (bid >> 3);   // heavy q-tiles first
    const int q0    = qt * 64;

    const int tid = threadIdx.x;
    const int ty  = tid >> 4;         // 0..15 -> rows ty*4..+3
    const int tx  = tid & 15;         // 0..15 -> cols tx*4..+3

    const float* qb = g_q + (size_t)batch * SEQ * HD;
    const float* kb = g_k + (size_t)batch * SEQ * HD;
    const float* vb = g_v + (size_t)batch * SEQ * HD;

    // Transposed-store mapping for Q/K: col-spread => conflict-free STS.32
    const int tcol = tid & 63;          // seq index within tile
    const int td0  = (tid >> 6) * 16;   // d-chunk start (0,16,32,48)
    // V mapping: row-major
    const int vr  = tid >> 2;           // 0..63
    const int vd0 = (tid & 3) * 16;

    // Load Q transposed (scaled)
    {
#pragma unroll
        for (int i = 0; i < 4; i++) {
            float4 v = *(const float4*)&qb[(size_t)(q0 + tcol) * HD + td0 + i * 4];
            Qt[(td0 + i * 4 + 0) * 64 + tcol] = v.x * SCALE;
            Qt[(td0 + i * 4 + 1) * 64 + tcol] = v.y * SCALE;
            Qt[(td0 + i * 4 + 2) * 64 + tcol] = v.z * SCALE;
            Qt[(td0 + i * 4 + 3) * 64 + tcol] = v.w * SCALE;
        }
    }

    float m_i[4] = {-1e30f, -1e30f, -1e30f, -1e30f};
    float l_i[4] = {0.f, 0.f, 0.f, 0.f};
    u64 acc2[4][2] = {};

    for (int kt = 0; kt <= qt; kt++) {
        const int k0 = kt * 64;

        // stage K/V global loads (latency hides under the sync)
        float4 kreg[4], vreg[4];
#pragma unroll
        for (int i = 0; i < 4; i++) {
            kreg[i] = *(const float4*)&kb[(size_t)(k0 + tcol) * HD + td0 + i * 4];
            vreg[i] = *(const float4*)&vb[(size_t)(k0 + vr) * HD + vd0 + i * 4];
        }
        __syncthreads();   // prev-iter PV reads of Vs/Ps done (and Qt visible at kt==0)
#pragma unroll
        for (int i = 0; i < 4; i++) {
            Kt[(td0 + i * 4 + 0) * 64 + tcol] = kreg[i].x;
            Kt[(td0 + i * 4 + 1) * 64 + tcol] = kreg[i].y;
            Kt[(td0 + i * 4 + 2) * 64 + tcol] = kreg[i].z;
            Kt[(td0 + i * 4 + 3) * 64 + tcol] = kreg[i].w;
            *(float4*)&Vs[vr * VSTR + vd0 + i * 4] = vreg[i];
        }
        __syncthreads();   // K/V tiles visible

        // S = Q K^T  (4x4 microtile, f32x2)
        u64 s2[4][2] = {};
#pragma unroll
        for (int d = 0; d < 64; d++) {
            float4 qv = *(const float4*)&Qt[d * 64 + ty * 4];
            ulonglong2 kp = *(const ulonglong2*)&Kt[d * 64 + tx * 4];
            float qa[4] = {qv.x, qv.y, qv.z, qv.w};
#pragma unroll
            for (int i = 0; i < 4; i++) {
                u64 ad = pk2(qa[i]);
                fma2(s2[i][0], ad, kp.x);
                fma2(s2[i][1], ad, kp.y);
            }
        }

        // softmax update fully in registers (16-lane row groups)
#pragma unroll
        for (int i = 0; i < 4; i++) {
            float2 u0 = up2(s2[i][0]);
            float2 u1 = up2(s2[i][1]);
            float s0 = u0.x, ss1 = u0.y, s2v = u1.x, s3 = u1.y;
            if (kt == qt) {
                const int qrow = q0 + ty * 4 + i;
                const int col  = k0 + tx * 4;
                if (col + 0 > qrow) s0  = -1e30f;
                if (col + 1 > qrow) ss1 = -1e30f;
                if (col + 2 > qrow) s2v = -1e30f;
                if (col + 3 > qrow) s3  = -1e30f;
            }
            float pm = fmaxf(fmaxf(s0, ss1), fmaxf(s2v, s3));
            pm = fmaxf(pm, __shfl_xor_sync(0xffffffffu, pm, 1));
            pm = fmaxf(pm, __shfl_xor_sync(0xffffffffu, pm, 2));
            pm = fmaxf(pm, __shfl_xor_sync(0xffffffffu, pm, 4));
            pm = fmaxf(pm, __shfl_xor_sync(0xffffffffu, pm, 8));
            const float mn = fmaxf(m_i[i], pm);
            const float cc = __expf(m_i[i] - mn);
            m_i[i] = mn;
            float p0 = __expf(s0  - mn);
            float p1 = __expf(ss1 - mn);
            float p2 = __expf(s2v - mn);
            float p3 = __expf(s3  - mn);
            *(float4*)&Ps[(ty * 4 + i) * PSTR + tx * 4] = make_float4(p0, p1, p2, p3);
            float ps = (p0 + p1) + (p2 + p3);
            ps += __shfl_xor_sync(0xffffffffu, ps, 1);
            ps += __shfl_xor_sync(0xffffffffu, ps, 2);
            ps += __shfl_xor_sync(0xffffffffu, ps, 4);
            ps += __shfl_xor_sync(0xffffffffu, ps, 8);
            l_i[i] = l_i[i] * cc + ps;
            u64 c2 = pk2(cc);
            mul2(acc2[i][0], acc2[i][0], c2);
            mul2(acc2[i][1], acc2[i][1], c2);
        }
        __syncthreads();   // Ps visible

        // O += P V   (f32x2)
#pragma unroll
        for (int k4 = 0; k4 < 64; k4 += 4) {
            float4 p[4];
#pragma unroll
            for (int i = 0; i < 4; i++)
                p[i] = *(const float4*)&Ps[(ty * 4 + i) * PSTR + k4];
#pragma unroll
            for (int j = 0; j < 4; j++) {
                ulonglong2 vp = *(const ulonglong2*)&Vs[(k4 + j) * VSTR + tx * 4];
#pragma unroll
                for (int i = 0; i < 4; i++) {
                    float pij = (j == 0) ? p[i].x : (j == 1) ? p[i].y
                              : (j == 2) ? p[i].z : p[i].w;
                    u64 pd = pk2(pij);
                    fma2(acc2[i][0], pd, vp.x);
                    fma2(acc2[i][1], pd, vp.y);
                }
            }
        }
    }

    // Epilogue (l_i in registers; no sync needed)
#pragma unroll
    for (int i = 0; i < 4; i++) {
        const int qr = q0 + ty * 4 + i;
        const float inv = 1.f / l_i[i];
        float2 o0 = up2(acc2[i][0]);
        float2 o1 = up2(acc2[i][1]);
        float4 o = make_float4(o0.x * inv, o0.y * inv, o1.x * inv, o1.y * inv);
        *(float4*)&out[(size_t)batch * SEQ * HD + (size_t)qr * HD + tx * 4] = o;
    }
}

// ---------------------------------------------------------------------------
extern "C" void kernel_launch(void* const* d_in, const int* in_sizes, int n_in,
                              void* d_out, int out_size)
{
    const float* x  = (const float*)d_in[0];
    const float* Wq = (const float*)d_in[1];
    const float* Wk = (const float*)d_in[2];
    const float* Wv = (const float*)d_in[3];
    float* out = (float*)d_out;

    static bool attr_set = false;
    if (!attr_set) {
        cudaFuncSetAttribute(attn_kernel,
                             cudaFuncAttributeMaxDynamicSharedMemorySize,
                             ATTN_SMEM_BYTES);
        attr_set = true;
    }

    dim3 g1(MROWS / 128, 3);
    qkv_kernel<<<g1, 128>>>(x, Wq, Wk, Wv);

    attn_kernel<<<BATCH * 32, 256, ATTN_SMEM_BYTES>>>(out);
}

// round 5
// speedup vs baseline: 1.4750x; 1.4006x over previous
#include <cuda_runtime.h>
#include <cuda_bf16.h>
#include <cstdint>

// Problem constants
#define BATCH 8
#define SEQ   2048
#define EMB   1024
#define HD    64
#define MROWS (BATCH*SEQ)      // 16384
#define SCALE 0.03125f         // 1024^-0.5

// Scratch (device globals: no allocation allowed)
// Q pre-scaled by SCALE; all stored as bf16 hi + lo (hi+lo ~= fp32 value)
__device__ __nv_bfloat16 g_qh[MROWS*HD];
__device__ __nv_bfloat16 g_ql[MROWS*HD];
__device__ __nv_bfloat16 g_kh[MROWS*HD];
__device__ __nv_bfloat16 g_kl[MROWS*HD];
__device__ __nv_bfloat16 g_vh[MROWS*HD];
__device__ __nv_bfloat16 g_vl[MROWS*HD];

// ---------------------------------------------------------------------------
// helpers
// ---------------------------------------------------------------------------
typedef unsigned long long u64;

__device__ __forceinline__ u64 pk2(float v) {
    u64 r;
    asm("mov.b64 %0, {%1, %1};" : "=l"(r) : "f"(v));
    return r;
}
__device__ __forceinline__ void fma2(u64& d, u64 a, u64 b) {
    asm("fma.rn.f32x2 %0, %1, %2, %3;" : "=l"(d) : "l"(a), "l"(b), "l"(d));
}
__device__ __forceinline__ float2 up2(u64 v) {
    float2 f;
    asm("mov.b64 {%0, %1}, %2;" : "=f"(f.x), "=f"(f.y) : "l"(v));
    return f;
}
// pack: upper half <- bf16(hi_val), lower half <- bf16(lo_val)
__device__ __forceinline__ uint32_t pkbf(float hi_val, float lo_val) {
    uint32_t d;
    asm("cvt.rn.bf16x2.f32 %0, %1, %2;" : "=r"(d) : "f"(hi_val), "f"(lo_val));
    return d;
}
__device__ __forceinline__ uint32_t smem_u32(const void* p) {
    uint32_t a;
    asm("{ .reg .u64 t; cvta.to.shared.u64 t, %1; cvt.u32.u64 %0, t; }"
        : "=r"(a) : "l"(p));
    return a;
}
__device__ __forceinline__ void ldsm4(uint32_t* r, uint32_t addr) {
    asm volatile("ldmatrix.sync.aligned.m8n8.x4.shared.b16 {%0,%1,%2,%3}, [%4];"
        : "=r"(r[0]), "=r"(r[1]), "=r"(r[2]), "=r"(r[3]) : "r"(addr));
}
__device__ __forceinline__ void ldsm4t(uint32_t* r, uint32_t addr) {
    asm volatile("ldmatrix.sync.aligned.m8n8.x4.trans.shared.b16 {%0,%1,%2,%3}, [%4];"
        : "=r"(r[0]), "=r"(r[1]), "=r"(r[2]), "=r"(r[3]) : "r"(addr));
}
__device__ __forceinline__ void mma16816(float* d, const uint32_t* a,
                                         uint32_t b0, uint32_t b1) {
    asm volatile(
        "mma.sync.aligned.m16n8k16.row.col.f32.bf16.bf16.f32 "
        "{%0,%1,%2,%3}, {%4,%5,%6,%7}, {%8,%9}, {%0,%1,%2,%3};"
        : "+f"(d[0]), "+f"(d[1]), "+f"(d[2]), "+f"(d[3])
        : "r"(a[0]), "r"(a[1]), "r"(a[2]), "r"(a[3]), "r"(b0), "r"(b1));
}

// ---------------------------------------------------------------------------
// Kernel 1: QKV projection (f32x2 core), epilogue writes bf16 hi/lo.
// grid = (MROWS/128, 3), block = 128.
// ---------------------------------------------------------------------------
__global__ __launch_bounds__(128) void qkv_kernel(
    const float* __restrict__ x,
    const float* __restrict__ Wq,
    const float* __restrict__ Wk,
    const float* __restrict__ Wv)
{
    __shared__ float a[2][16][128];
    __shared__ float b[2][16][72];

    const int y = blockIdx.y;
    const float* W = (y == 0) ? Wq : (y == 1) ? Wk : Wv;
    __nv_bfloat16* oh = (y == 0) ? g_qh : (y == 1) ? g_kh : g_vh;
    __nv_bfloat16* ol = (y == 0) ? g_ql : (y == 1) ? g_kl : g_vl;
    const float scale = (y == 0) ? SCALE : 1.0f;

    const int row0 = blockIdx.x * 128;
    const int tid  = threadIdx.x;
    const int ty   = tid >> 3;
    const int tx   = tid & 7;

    const int bk0 = (tid * 2) >> 4;
    const int bn0 = ((tid * 2) & 15) * 4;
    const int bk1 = (tid * 2 + 1) >> 4;
    const int bn1 = ((tid * 2 + 1) & 15) * 4;

    u64 acc2[8][4] = {};

    float4 av[4], bv0, bv1;
#pragma unroll
    for (int j = 0; j < 4; j++)
        av[j] = *(const float4*)&x[(size_t)(row0 + tid) * EMB + j * 4];
    bv0 = *(const float4*)&W[(size_t)bk0 * HD + bn0];
    bv1 = *(const float4*)&W[(size_t)bk1 * HD + bn1];
#pragma unroll
    for (int j = 0; j < 4; j++) {
        a[0][j * 4 + 0][tid] = av[j].x;
        a[0][j * 4 + 1][tid] = av[j].y;
        a[0][j * 4 + 2][tid] = av[j].z;
        a[0][j * 4 + 3][tid] = av[j].w;
    }
    *(float4*)&b[0][bk0][bn0] = bv0;
    *(float4*)&b[0][bk1][bn1] = bv1;

    for (int c = 0; c < 64; c++) {
        const int cur = c & 1;
        if (c < 63) {
            const int k0 = (c + 1) * 16;
#pragma unroll
            for (int j = 0; j < 4; j++)
                av[j] = *(const float4*)&x[(size_t)(row0 + tid) * EMB + k0 + j * 4];
            bv0 = *(const float4*)&W[(size_t)(k0 + bk0) * HD + bn0];
            bv1 = *(const float4*)&W[(size_t)(k0 + bk1) * HD + bn1];
        }
        __syncthreads();
        if (c < 63) {
            const int nb = cur ^ 1;
#pragma unroll
            for (int j = 0; j < 4; j++) {
                a[nb][j * 4 + 0][tid] = av[j].x;
                a[nb][j * 4 + 1][tid] = av[j].y;
                a[nb][j * 4 + 2][tid] = av[j].z;
                a[nb][j * 4 + 3][tid] = av[j].w;
            }
            *(float4*)&b[nb][bk0][bn0] = bv0;
            *(float4*)&b[nb][bk1][bn1] = bv1;
        }

#pragma unroll
        for (int kk = 0; kk < 16; kk++) {
            float4 a0 = *(const float4*)&a[cur][kk][ty * 8];
            float4 a1 = *(const float4*)&a[cur][kk][ty * 8 + 4];
            ulonglong2 b0 = *(const ulonglong2*)&b[cur][kk][tx * 8];
            ulonglong2 b1 = *(const ulonglong2*)&b[cur][kk][tx * 8 + 4];
            float aa[8] = {a0.x, a0.y, a0.z, a0.w, a1.x, a1.y, a1.z, a1.w};
#pragma unroll
            for (int i = 0; i < 8; i++) {
                u64 ad = pk2(aa[i]);
                fma2(acc2[i][0], ad, b0.x);
                fma2(acc2[i][1], ad, b0.y);
                fma2(acc2[i][2], ad, b1.x);
                fma2(acc2[i][3], ad, b1.y);
            }
        }
    }

    // epilogue: split into bf16 hi + lo
#pragma unroll
    for (int i = 0; i < 8; i++) {
        float2 p0 = up2(acc2[i][0]), p1 = up2(acc2[i][1]);
        float2 p2 = up2(acc2[i][2]), p3 = up2(acc2[i][3]);
        float v[8] = {p0.x, p0.y, p1.x, p1.y, p2.x, p2.y, p3.x, p3.y};
        float lo[8];
#pragma unroll
        for (int j = 0; j < 8; j++) {
            v[j] *= scale;
            lo[j] = v[j] - __bfloat162float(__float2bfloat16(v[j]));
        }
        uint4 hb = make_uint4(pkbf(v[1], v[0]),  pkbf(v[3], v[2]),
                              pkbf(v[5], v[4]),  pkbf(v[7], v[6]));
        uint4 lb = make_uint4(pkbf(lo[1], lo[0]), pkbf(lo[3], lo[2]),
                              pkbf(lo[5], lo[4]), pkbf(lo[7], lo[6]));
        const size_t off = (size_t)(row0 + ty * 8 + i) * HD + tx * 8;
        *(uint4*)&oh[off] = hb;
        *(uint4*)&ol[off] = lb;
    }
}

// ---------------------------------------------------------------------------
// Kernel 2: causal flash attention on mma.sync bf16 (hi/lo split).
// 128 threads (4 warps x 16 q-rows), q-tile 64, k-tile 64.
// grid = 256 (batch x 32 q-tiles, heavy first).
// ---------------------------------------------------------------------------
#define SROW 72                       // smem row stride in bf16 elems
#define ATTN_SMEM_BYTES (6 * 64 * SROW * 2)   // Kh,Kl,Vh,Vl,Qh,Ql = 55296

__global__ __launch_bounds__(128) void attn_kernel(float* __restrict__ out)
{
    extern __shared__ __nv_bfloat16 smb[];
    __nv_bfloat16* sKh = smb;
    __nv_bfloat16* sKl = smb + 64 * SROW;
    __nv_bfloat16* sVh = smb + 2 * 64 * SROW;
    __nv_bfloat16* sVl = smb + 3 * 64 * SROW;
    __nv_bfloat16* sQh = smb + 4 * 64 * SROW;
    __nv_bfloat16* sQl = smb + 5 * 64 * SROW;

    const uint32_t uKh = smem_u32(sKh);
    const uint32_t uKl = smem_u32(sKl);
    const uint32_t uVh = smem_u32(sVh);
    const uint32_t uVl = smem_u32(sVl);
    const uint32_t uQh = smem_u32(sQh);
    const uint32_t uQl = smem_u32(sQl);

    const int bid   = blockIdx.x;
    const int batch = bid & 7;
    const int qt    = 31 - (bid >> 3);   // heavy q-tiles first
    const int q0    = qt * 64;

    const int tid  = threadIdx.x;
    const int wq   = tid >> 5;          // warp 0..3, q rows wq*16..+15
    const int lane = tid & 31;
    const int g    = lane >> 2;         // 0..7
    const int tg   = lane & 3;          // 0..3
    const int m4   = lane >> 3;         // ldmatrix matrix id 0..3
    const int r8   = lane & 7;

    const size_t bb = (size_t)batch * SEQ * HD;
    const __nv_bfloat16* gqh = g_qh + bb;
    const __nv_bfloat16* gql = g_ql + bb;
    const __nv_bfloat16* gkh = g_kh + bb;
    const __nv_bfloat16* gkl = g_kl + bb;
    const __nv_bfloat16* gvh = g_vh + bb;
    const __nv_bfloat16* gvl = g_vl + bb;

    // staging mapping: thread -> (row, 32-elem half-row)
    const int srow = tid >> 1;
    const int scol = (tid & 1) * 32;

    // ---- stage Q, build Q fragments (once) ----
    {
        const uint4* sh = (const uint4*)(gqh + (size_t)(q0 + srow) * HD + scol);
        const uint4* sl = (const uint4*)(gql + (size_t)(q0 + srow) * HD + scol);
        uint4 th[4], tl[4];
#pragma unroll
        for (int j = 0; j < 4; j++) { th[j] = sh[j]; tl[j] = sl[j]; }
#pragma unroll
        for (int j = 0; j < 4; j++) {
            *(uint4*)(sQh + srow * SROW + scol + 8 * j) = th[j];
            *(uint4*)(sQl + srow * SROW + scol + 8 * j) = tl[j];
        }
    }
    __syncthreads();

    uint32_t qh[4][4], ql[4][4];
    {
        const int qrow = wq * 16 + ((m4 & 1) << 3) + r8;
#pragma unroll
        for (int kc = 0; kc < 4; kc++) {
            uint32_t off = (uint32_t)(qrow * (SROW * 2) + (kc * 16 + (m4 >> 1) * 8) * 2);
            ldsm4(qh[kc], uQh + off);
            ldsm4(ql[kc], uQl + off);
        }
    }

    float o[8][4] = {};
    float m0 = -1e30f, m1 = -1e30f;
    float l0 = 0.f, l1 = 0.f;
    const int qrow0 = q0 + wq * 16 + g;
    const int qrow1 = qrow0 + 8;

    for (int kt = 0; kt <= qt; kt++) {
        const int k0 = kt * 64;

        // ---- stage K/V (prefetch into regs, 2 syncs) ----
        uint4 pf[16];
        {
            const uint4* s0 = (const uint4*)(gkh + (size_t)(k0 + srow) * HD + scol);
            const uint4* s1 = (const uint4*)(gkl + (size_t)(k0 + srow) * HD + scol);
            const uint4* s2 = (const uint4*)(gvh + (size_t)(k0 + srow) * HD + scol);
            const uint4* s3 = (const uint4*)(gvl + (size_t)(k0 + srow) * HD + scol);
#pragma unroll
            for (int j = 0; j < 4; j++) {
                pf[j]      = s0[j];
                pf[4 + j]  = s1[j];
                pf[8 + j]  = s2[j];
                pf[12 + j] = s3[j];
            }
        }
        __syncthreads();   // prior LDSM reads done
#pragma unroll
        for (int j = 0; j < 4; j++) {
            *(uint4*)(sKh + srow * SROW + scol + 8 * j) = pf[j];
            *(uint4*)(sKl + srow * SROW + scol + 8 * j) = pf[4 + j];
            *(uint4*)(sVh + srow * SROW + scol + 8 * j) = pf[8 + j];
            *(uint4*)(sVl + srow * SROW + scol + 8 * j) = pf[12 + j];
        }
        __syncthreads();   // tiles visible

        // ---- S = Q K^T (bf16 split: Qh·Kh + Qh·Kl + Ql·Kh) ----
        float sf[8][4];
#pragma unroll
        for (int nf = 0; nf < 8; nf++) {
            sf[nf][0] = sf[nf][1] = sf[nf][2] = sf[nf][3] = 0.f;
#pragma unroll
            for (int kcb = 0; kcb < 4; kcb += 2) {
                uint32_t bh[4], bl[4];
                uint32_t off = (uint32_t)((nf * 8 + r8) * (SROW * 2) +
                               (kcb * 16 + (m4 & 1) * 8 + (m4 >> 1) * 16) * 2);
                ldsm4(bh, uKh + off);
                ldsm4(bl, uKl + off);
                mma16816(sf[nf], qh[kcb],     bh[0], bh[1]);
                mma16816(sf[nf], qh[kcb],     bl[0], bl[1]);
                mma16816(sf[nf], ql[kcb],     bh[0], bh[1]);
                mma16816(sf[nf], qh[kcb + 1], bh[2], bh[3]);
                mma16816(sf[nf], qh[kcb + 1], bl[2], bl[3]);
                mma16816(sf[nf], ql[kcb + 1], bh[2], bh[3]);
            }
        }

        // ---- causal mask (diagonal tile) ----
        if (kt == qt) {
#pragma unroll
            for (int nf = 0; nf < 8; nf++) {
                const int col = k0 + nf * 8 + 2 * tg;
                if (col     > qrow0) sf[nf][0] = -1e30f;
                if (col + 1 > qrow0) sf[nf][1] = -1e30f;
                if (col     > qrow1) sf[nf][2] = -1e30f;
                if (col + 1 > qrow1) sf[nf][3] = -1e30f;
            }
        }

        // ---- online softmax (rows g, g+8; 4-lane shfl groups) ----
        float mx0 = -1e30f, mx1 = -1e30f;
#pragma unroll
        for (int nf = 0; nf < 8; nf++) {
            mx0 = fmaxf(mx0, fmaxf(sf[nf][0], sf[nf][1]));
            mx1 = fmaxf(mx1, fmaxf(sf[nf][2], sf[nf][3]));
        }
        mx0 = fmaxf(mx0, __shfl_xor_sync(0xffffffffu, mx0, 1));
        mx0 = fmaxf(mx0, __shfl_xor_sync(0xffffffffu, mx0, 2));
        mx1 = fmaxf(mx1, __shfl_xor_sync(0xffffffffu, mx1, 1));
        mx1 = fmaxf(mx1, __shfl_xor_sync(0xffffffffu, mx1, 2));

        const float mn0 = fmaxf(m0, mx0);
        const float mn1 = fmaxf(m1, mx1);
        const float c0 = __expf(m0 - mn0);
        const float c1 = __expf(m1 - mn1);
        m0 = mn0; m1 = mn1;

        float sum0 = 0.f, sum1 = 0.f;
#pragma unroll
        for (int nf = 0; nf < 8; nf++) {
            sf[nf][0] = __expf(sf[nf][0] - mn0);
            sf[nf][1] = __expf(sf[nf][1] - mn0);
            sf[nf][2] = __expf(sf[nf][2] - mn1);
            sf[nf][3] = __expf(sf[nf][3] - mn1);
            sum0 += sf[nf][0] + sf[nf][1];
            sum1 += sf[nf][2] + sf[nf][3];
        }
        sum0 += __shfl_xor_sync(0xffffffffu, sum0, 1);
        sum0 += __shfl_xor_sync(0xffffffffu, sum0, 2);
        sum1 += __shfl_xor_sync(0xffffffffu, sum1, 1);
        sum1 += __shfl_xor_sync(0xffffffffu, sum1, 2);
        l0 = l0 * c0 + sum0;
        l1 = l1 * c1 + sum1;

#pragma unroll
        for (int nf = 0; nf < 8; nf++) {
            o[nf][0] *= c0; o[nf][1] *= c0;
            o[nf][2] *= c1; o[nf][3] *= c1;
        }

        // ---- P -> bf16 hi/lo A-fragments ----
        uint32_t ph[4][4], pl[4][4];
#pragma unroll
        for (int kc = 0; kc < 4; kc++) {
            const int f0 = 2 * kc, f1 = 2 * kc + 1;
            float r00 = sf[f0][0] - __bfloat162float(__float2bfloat16(sf[f0][0]));
            float r01 = sf[f0][1] - __bfloat162float(__float2bfloat16(sf[f0][1]));
            float r02 = sf[f0][2] - __bfloat162float(__float2bfloat16(sf[f0][2]));
            float r03 = sf[f0][3] - __bfloat162float(__float2bfloat16(sf[f0][3]));
            float r10 = sf[f1][0] - __bfloat162float(__float2bfloat16(sf[f1][0]));
            float r11 = sf[f1][1] - __bfloat162float(__float2bfloat16(sf[f1][1]));
            float r12 = sf[f1][2] - __bfloat162float(__float2bfloat16(sf[f1][2]));
            float r13 = sf[f1][3] - __bfloat162float(__float2bfloat16(sf[f1][3]));
            ph[kc][0] = pkbf(sf[f0][1], sf[f0][0]);
            ph[kc][1] = pkbf(sf[f0][3], sf[f0][2]);
            ph[kc][2] = pkbf(sf[f1][1], sf[f1][0]);
            ph[kc][3] = pkbf(sf[f1][3], sf[f1][2]);
            pl[kc][0] = pkbf(r01, r00);
            pl[kc][1] = pkbf(r03, r02);
            pl[kc][2] = pkbf(r11, r10);
            pl[kc][3] = pkbf(r13, r12);
        }

        // ---- O += P V (Ph·Vh + Ph·Vl + Pl·Vh), V via ldmatrix.trans ----
#pragma unroll
        for (int nf = 0; nf < 8; nf++) {
#pragma unroll
            for (int kcb = 0; kcb < 4; kcb += 2) {
                uint32_t bh[4], bl[4];
                uint32_t off = (uint32_t)((kcb * 16 + (m4 & 1) * 8 + (m4 >> 1) * 16 + r8)
                               * (SROW * 2) + nf * 16);
                ldsm4t(bh, uVh + off);
                ldsm4t(bl, uVl + off);
                mma16816(o[nf], ph[kcb],     bh[0], bh[1]);
                mma16816(o[nf], ph[kcb],     bl[0], bl[1]);
                mma16816(o[nf], pl[kcb],     bh[0], bh[1]);
                mma16816(o[nf], ph[kcb + 1], bh[2], bh[3]);
                mma16816(o[nf], ph[kcb + 1], bl[2], bl[3]);
                mma16816(o[nf], pl[kcb + 1], bh[2], bh[3]);
            }
        }
    }

    // ---- epilogue ----
    const float inv0 = 1.f / l0;
    const float inv1 = 1.f / l1;
    float* ob = out + (size_t)batch * SEQ * HD;
#pragma unroll
    for (int nf = 0; nf < 8; nf++) {
        *(float2*)&ob[(size_t)qrow0 * HD + nf * 8 + 2 * tg] =
            make_float2(o[nf][0] * inv0, o[nf][1] * inv0);
        *(float2*)&ob[(size_t)qrow1 * HD + nf * 8 + 2 * tg] =
            make_float2(o[nf][2] * inv1, o[nf][3] * inv1);
    }
}

// ---------------------------------------------------------------------------
extern "C" void kernel_launch(void* const* d_in, const int* in_sizes, int n_in,
                              void* d_out, int out_size)
{
    const float* x  = (const float*)d_in[0];
    const float* Wq = (const float*)d_in[1];
    const float* Wk = (const float*)d_in[2];
    const float* Wv = (const float*)d_in[3];
    float* out = (float*)d_out;

    static bool attr_set = false;
    if (!attr_set) {
        cudaFuncSetAttribute(attn_kernel,
                             cudaFuncAttributeMaxDynamicSharedMemorySize,
                             ATTN_SMEM_BYTES);
        attr_set = true;
    }

    dim3 g1(MROWS / 128, 3);
    qkv_kernel<<<g1, 128>>>(x, Wq, Wk, Wv);

    attn_kernel<<<BATCH * 32, 128, ATTN_SMEM_BYTES>>>(out);
}

// round 6
// speedup vs baseline: 2.3633x; 1.6023x over previous
#include <cuda_runtime.h>
#include <cuda_bf16.h>
#include <cstdint>

// Problem constants
#define BATCH 8
#define SEQ   2048
#define EMB   1024
#define HD    64
#define MROWS (BATCH*SEQ)      // 16384
#define SCALE 0.03125f         // 1024^-0.5

// Scratch (device globals: no allocation allowed)
// Q pre-scaled by SCALE; all stored as bf16 hi + lo (hi+lo ~= fp32 value)
__device__ __nv_bfloat16 g_qh[MROWS*HD];
__device__ __nv_bfloat16 g_ql[MROWS*HD];
__device__ __nv_bfloat16 g_kh[MROWS*HD];
__device__ __nv_bfloat16 g_kl[MROWS*HD];
__device__ __nv_bfloat16 g_vh[MROWS*HD];
__device__ __nv_bfloat16 g_vl[MROWS*HD];
// Weights in B-operand layout [192][1024] K-major, bf16 hi/lo
__device__ __nv_bfloat16 g_Bh[192*1024];
__device__ __nv_bfloat16 g_Bl[192*1024];

// ---------------------------------------------------------------------------
// helpers
// ---------------------------------------------------------------------------
// pack: upper half <- bf16(hi_val), lower half <- bf16(lo_val)
__device__ __forceinline__ uint32_t pkbf(float hi_val, float lo_val) {
    uint32_t d;
    asm("cvt.rn.bf16x2.f32 %0, %1, %2;" : "=r"(d) : "f"(hi_val), "f"(lo_val));
    return d;
}
__device__ __forceinline__ uint32_t smem_u32(const void* p) {
    uint32_t a;
    asm("{ .reg .u64 t; cvta.to.shared.u64 t, %1; cvt.u32.u64 %0, t; }"
        : "=r"(a) : "l"(p));
    return a;
}
__device__ __forceinline__ void ldsm4(uint32_t* r, uint32_t addr) {
    asm volatile("ldmatrix.sync.aligned.m8n8.x4.shared.b16 {%0,%1,%2,%3}, [%4];"
        : "=r"(r[0]), "=r"(r[1]), "=r"(r[2]), "=r"(r[3]) : "r"(addr));
}
__device__ __forceinline__ void ldsm4t(uint32_t* r, uint32_t addr) {
    asm volatile("ldmatrix.sync.aligned.m8n8.x4.trans.shared.b16 {%0,%1,%2,%3}, [%4];"
        : "=r"(r[0]), "=r"(r[1]), "=r"(r[2]), "=r"(r[3]) : "r"(addr));
}
__device__ __forceinline__ void mma16816(float* d, const uint32_t* a,
                                         uint32_t b0, uint32_t b1) {
    asm volatile(
        "mma.sync.aligned.m16n8k16.row.col.f32.bf16.bf16.f32 "
        "{%0,%1,%2,%3}, {%4,%5,%6,%7}, {%8,%9}, {%0,%1,%2,%3};"
        : "+f"(d[0]), "+f"(d[1]), "+f"(d[2]), "+f"(d[3])
        : "r"(a[0]), "r"(a[1]), "r"(a[2]), "r"(a[3]), "r"(b0), "r"(b1));
}
__device__ __forceinline__ float lo_of(float v) {
    return v - __bfloat162float(__float2bfloat16(v));
}

// ---------------------------------------------------------------------------
// Kernel 0: weight conversion -> [192][1024] K-major, bf16 hi/lo.
// grid = 1024 (one per k), block = 192 (one per n). Coalesced reads.
// ---------------------------------------------------------------------------
__global__ void conv_w_kernel(const float* __restrict__ Wq,
                              const float* __restrict__ Wk,
                              const float* __restrict__ Wv)
{
    const int k = blockIdx.x;
    const int n = threadIdx.x;
    const float* W = (n < 64) ? Wq : (n < 128) ? Wk : Wv;
    float v = W[k * 64 + (n & 63)];
    __nv_bfloat16 h = __float2bfloat16(v);
    g_Bh[n * 1024 + k] = h;
    g_Bl[n * 1024 + k] = __float2bfloat16(v - __bfloat162float(h));
}

// ---------------------------------------------------------------------------
// Kernel 1: QKV projection via mma.sync bf16 hi/lo split.
// grid = 128 (M tiles of 128), block = 256 (2x4 warp grid, 64Mx48N each).
// D[128x192] = Xh*Wh + Xh*Wl + Xl*Wh, K=1024 in BK=64 chunks, double-buffered.
// ---------------------------------------------------------------------------
#define QSTR 144                   // smem row stride bytes (72 bf16)
#define XH_OFF 0                   // elem offsets within one buffer
#define XL_OFF 9216                // 128*72
#define WH_OFF 18432
#define WL_OFF 32256               // 18432 + 192*72
#define QBUF_ELEMS 46080           // 32256 + 13824
#define QKV_SMEM_BYTES (2 * QBUF_ELEMS * 2)   // 184320

__global__ __launch_bounds__(256) void qkv_tc_kernel(const float* __restrict__ x)
{
    extern __shared__ __nv_bfloat16 qs[];
    const uint32_t uBase = smem_u32(qs);

    const int tid  = threadIdx.x;
    const int wid  = tid >> 5;
    const int lane = tid & 31;
    const int wm   = wid >> 2;       // 0..1 (M half)
    const int wn   = wid & 3;        // 0..3 (N quarter: 48 cols)
    const int m4   = lane >> 3;
    const int r8   = lane & 7;
    const int g    = lane >> 2;
    const int tg   = lane & 3;
    const int row0 = blockIdx.x * 128;

    // staging mapping
    const int xr  = tid >> 1;          // x row 0..127
    const int xc0 = (tid & 1) * 32;    // 32-elem half

    float acc[4][6][4] = {};
    float4 xv[8];
    uint4  wh6[6], wl6[6];

#define LOADX(c) do { \
    _Pragma("unroll") \
    for (int j = 0; j < 8; j++) \
        xv[j] = *(const float4*)&x[(size_t)(row0 + xr) * EMB + (c) * 64 + xc0 + j * 4]; \
    _Pragma("unroll") \
    for (int j = 0; j < 6; j++) { \
        int gi = tid + j * 256; \
        int rw = gi >> 3, sg = gi & 7; \
        wh6[j] = *(const uint4*)&g_Bh[rw * 1024 + (c) * 64 + sg * 8]; \
        wl6[j] = *(const uint4*)&g_Bl[rw * 1024 + (c) * 64 + sg * 8]; \
    } \
} while (0)

#define STOREB(b) do { \
    __nv_bfloat16* base = qs + (b) * QBUF_ELEMS; \
    _Pragma("unroll") \
    for (int j = 0; j < 8; j++) { \
        uint32_t h0 = pkbf(xv[j].y, xv[j].x); \
        uint32_t h1 = pkbf(xv[j].w, xv[j].z); \
        uint32_t l0 = pkbf(lo_of(xv[j].y), lo_of(xv[j].x)); \
        uint32_t l1 = pkbf(lo_of(xv[j].w), lo_of(xv[j].z)); \
        *(uint2*)(base + XH_OFF + xr * 72 + xc0 + j * 4) = make_uint2(h0, h1); \
        *(uint2*)(base + XL_OFF + xr * 72 + xc0 + j * 4) = make_uint2(l0, l1); \
    } \
    _Pragma("unroll") \
    for (int j = 0; j < 6; j++) { \
        int gi = tid + j * 256; \
        int rw = gi >> 3, sg = gi & 7; \
        *(uint4*)(base + WH_OFF + rw * 72 + sg * 8) = wh6[j]; \
        *(uint4*)(base + WL_OFF + rw * 72 + sg * 8) = wl6[j]; \
    } \
} while (0)

    // prologue
    LOADX(0);
    STOREB(0);

    for (int c = 0; c < 16; c++) {
        const int cur = c & 1;
        if (c < 15) LOADX(c + 1);
        __syncthreads();
        if (c < 15) STOREB(cur ^ 1);

        const uint32_t uB  = uBase + cur * (QBUF_ELEMS * 2);
        const uint32_t uXh = uB + XH_OFF * 2;
        const uint32_t uXl = uB + XL_OFF * 2;
        const uint32_t uWh = uB + WH_OFF * 2;
        const uint32_t uWl = uB + WL_OFF * 2;

#pragma unroll
        for (int kcb = 0; kcb < 4; kcb += 2) {
            uint32_t ah[4][2][4], al[4][2][4];
#pragma unroll
            for (int mf = 0; mf < 4; mf++)
#pragma unroll
                for (int kk = 0; kk < 2; kk++) {
                    uint32_t off = (uint32_t)((wm * 64 + mf * 16 + (m4 & 1) * 8 + r8) * QSTR
                                   + ((kcb + kk) * 16 + (m4 >> 1) * 8) * 2);
                    ldsm4(ah[mf][kk], uXh + off);
                    ldsm4(al[mf][kk], uXl + off);
                }
#pragma unroll
            for (int nf = 0; nf < 6; nf++) {
                uint32_t bh[4], bl[4];
                uint32_t off = (uint32_t)((wn * 48 + nf * 8 + r8) * QSTR
                               + (kcb * 16 + (m4 & 1) * 8 + (m4 >> 1) * 16) * 2);
                ldsm4(bh, uWh + off);
                ldsm4(bl, uWl + off);
#pragma unroll
                for (int mf = 0; mf < 4; mf++) {
                    mma16816(acc[mf][nf], ah[mf][0], bh[0], bh[1]);
                    mma16816(acc[mf][nf], ah[mf][0], bl[0], bl[1]);
                    mma16816(acc[mf][nf], al[mf][0], bh[0], bh[1]);
                    mma16816(acc[mf][nf], ah[mf][1], bh[2], bh[3]);
                    mma16816(acc[mf][nf], ah[mf][1], bl[2], bl[3]);
                    mma16816(acc[mf][nf], al[mf][1], bh[2], bh[3]);
                }
            }
        }
    }

    // epilogue: split accumulators into bf16 hi/lo, route to q/k/v
#pragma unroll
    for (int mf = 0; mf < 4; mf++) {
        const int r0 = row0 + wm * 64 + mf * 16 + g;
#pragma unroll
        for (int nf = 0; nf < 6; nf++) {
            const int n   = wn * 48 + nf * 8 + 2 * tg;
            const int mat = n >> 6;
            const int lc  = n & 63;
            __nv_bfloat16* oh = (mat == 0) ? g_qh : (mat == 1) ? g_kh : g_vh;
            __nv_bfloat16* ol = (mat == 0) ? g_ql : (mat == 1) ? g_kl : g_vl;
            const float sc = (mat == 0) ? SCALE : 1.0f;
            float v0 = acc[mf][nf][0] * sc, v1 = acc[mf][nf][1] * sc;
            float v2 = acc[mf][nf][2] * sc, v3 = acc[mf][nf][3] * sc;
            *(uint32_t*)&oh[(size_t)r0 * 64 + lc]       = pkbf(v1, v0);
            *(uint32_t*)&ol[(size_t)r0 * 64 + lc]       = pkbf(lo_of(v1), lo_of(v0));
            *(uint32_t*)&oh[(size_t)(r0 + 8) * 64 + lc] = pkbf(v3, v2);
            *(uint32_t*)&ol[(size_t)(r0 + 8) * 64 + lc] = pkbf(lo_of(v3), lo_of(v2));
        }
    }
#undef LOADX
#undef STOREB
}

// ---------------------------------------------------------------------------
// Kernel 2: causal flash attention on mma.sync bf16 (hi/lo split).
// 128 threads (4 warps x 16 q-rows), q-tile 64, k-tile 64.
// grid = 256 (batch x 32 q-tiles, heavy first).
// ---------------------------------------------------------------------------
#define SROW 72                       // smem row stride in bf16 elems
#define ATTN_SMEM_BYTES (6 * 64 * SROW * 2)   // Kh,Kl,Vh,Vl,Qh,Ql = 55296

__global__ __launch_bounds__(128) void attn_kernel(float* __restrict__ out)
{
    extern __shared__ __nv_bfloat16 smb[];
    __nv_bfloat16* sKh = smb;
    __nv_bfloat16* sKl = smb + 64 * SROW;
    __nv_bfloat16* sVh = smb + 2 * 64 * SROW;
    __nv_bfloat16* sVl = smb + 3 * 64 * SROW;
    __nv_bfloat16* sQh = smb + 4 * 64 * SROW;
    __nv_bfloat16* sQl = smb + 5 * 64 * SROW;

    const uint32_t uKh = smem_u32(sKh);
    const uint32_t uKl = smem_u32(sKl);
    const uint32_t uVh = smem_u32(sVh);
    const uint32_t uVl = smem_u32(sVl);
    const uint32_t uQh = smem_u32(sQh);
    const uint32_t uQl = smem_u32(sQl);

    const int bid   = blockIdx.x;
    const int batch = bid & 7;
    const int qt    = 31 - (bid >> 3);   // heavy q-tiles first
    const int q0    = qt * 64;

    const int tid  = threadIdx.x;
    const int wq   = tid >> 5;          // warp 0..3, q rows wq*16..+15
    const int lane = tid & 31;
    const int g    = lane >> 2;         // 0..7
    const int tg   = lane & 3;          // 0..3
    const int m4   = lane >> 3;         // ldmatrix matrix id 0..3
    const int r8   = lane & 7;

    const size_t bb = (size_t)batch * SEQ * HD;
    const __nv_bfloat16* gqh = g_qh + bb;
    const __nv_bfloat16* gql = g_ql + bb;
    const __nv_bfloat16* gkh = g_kh + bb;
    const __nv_bfloat16* gkl = g_kl + bb;
    const __nv_bfloat16* gvh = g_vh + bb;
    const __nv_bfloat16* gvl = g_vl + bb;

    // staging mapping: thread -> (row, 32-elem half-row)
    const int srow = tid >> 1;
    const int scol = (tid & 1) * 32;

    // ---- stage Q, build Q fragments (once) ----
    {
        const uint4* sh = (const uint4*)(gqh + (size_t)(q0 + srow) * HD + scol);
        const uint4* sl = (const uint4*)(gql + (size_t)(q0 + srow) * HD + scol);
        uint4 th[4], tl[4];
#pragma unroll
        for (int j = 0; j < 4; j++) { th[j] = sh[j]; tl[j] = sl[j]; }
#pragma unroll
        for (int j = 0; j < 4; j++) {
            *(uint4*)(sQh + srow * SROW + scol + 8 * j) = th[j];
            *(uint4*)(sQl + srow * SROW + scol + 8 * j) = tl[j];
        }
    }
    __syncthreads();

    uint32_t qh[4][4], ql[4][4];
    {
        const int qrow = wq * 16 + ((m4 & 1) << 3) + r8;
#pragma unroll
        for (int kc = 0; kc < 4; kc++) {
            uint32_t off = (uint32_t)(qrow * (SROW * 2) + (kc * 16 + (m4 >> 1) * 8) * 2);
            ldsm4(qh[kc], uQh + off);
            ldsm4(ql[kc], uQl + off);
        }
    }

    float o[8][4] = {};
    float m0 = -1e30f, m1 = -1e30f;
    float l0 = 0.f, l1 = 0.f;
    const int qrow0 = q0 + wq * 16 + g;
    const int qrow1 = qrow0 + 8;

    for (int kt = 0; kt <= qt; kt++) {
        const int k0 = kt * 64;

        // ---- stage K/V (prefetch into regs, 2 syncs) ----
        uint4 pf[16];
        {
            const uint4* s0 = (const uint4*)(gkh + (size_t)(k0 + srow) * HD + scol);
            const uint4* s1 = (const uint4*)(gkl + (size_t)(k0 + srow) * HD + scol);
            const uint4* s2 = (const uint4*)(gvh + (size_t)(k0 + srow) * HD + scol);
            const uint4* s3 = (const uint4*)(gvl + (size_t)(k0 + srow) * HD + scol);
#pragma unroll
            for (int j = 0; j < 4; j++) {
                pf[j]      = s0[j];
                pf[4 + j]  = s1[j];
                pf[8 + j]  = s2[j];
                pf[12 + j] = s3[j];
            }
        }
        __syncthreads();   // prior LDSM reads done
#pragma unroll
        for (int j = 0; j < 4; j++) {
            *(uint4*)(sKh + srow * SROW + scol + 8 * j) = pf[j];
            *(uint4*)(sKl + srow * SROW + scol + 8 * j) = pf[4 + j];
            *(uint4*)(sVh + srow * SROW + scol + 8 * j) = pf[8 + j];
            *(uint4*)(sVl + srow * SROW + scol + 8 * j) = pf[12 + j];
        }
        __syncthreads();   // tiles visible

        // ---- S = Q K^T (bf16 split: Qh·Kh + Qh·Kl + Ql·Kh) ----
        float sf[8][4];
#pragma unroll
        for (int nf = 0; nf < 8; nf++) {
            sf[nf][0] = sf[nf][1] = sf[nf][2] = sf[nf][3] = 0.f;
#pragma unroll
            for (int kcb = 0; kcb < 4; kcb += 2) {
                uint32_t bh[4], bl[4];
                uint32_t off = (uint32_t)((nf * 8 + r8) * (SROW * 2) +
                               (kcb * 16 + (m4 & 1) * 8 + (m4 >> 1) * 16) * 2);
                ldsm4(bh, uKh + off);
                ldsm4(bl, uKl + off);
                mma16816(sf[nf], qh[kcb],     bh[0], bh[1]);
                mma16816(sf[nf], qh[kcb],     bl[0], bl[1]);
                mma16816(sf[nf], ql[kcb],     bh[0], bh[1]);
                mma16816(sf[nf], qh[kcb + 1], bh[2], bh[3]);
                mma16816(sf[nf], qh[kcb + 1], bl[2], bl[3]);
                mma16816(sf[nf], ql[kcb + 1], bh[2], bh[3]);
            }
        }

        // ---- causal mask (diagonal tile) ----
        if (kt == qt) {
#pragma unroll
            for (int nf = 0; nf < 8; nf++) {
                const int col = k0 + nf * 8 + 2 * tg;
                if (col     > qrow0) sf[nf][0] = -1e30f;
                if (col + 1 > qrow0) sf[nf][1] = -1e30f;
                if (col     > qrow1) sf[nf][2] = -1e30f;
                if (col + 1 > qrow1) sf[nf][3] = -1e30f;
            }
        }

        // ---- online softmax (rows g, g+8; 4-lane shfl groups) ----
        float mx0 = -1e30f, mx1 = -1e30f;
#pragma unroll
        for (int nf = 0; nf < 8; nf++) {
            mx0 = fmaxf(mx0, fmaxf(sf[nf][0], sf[nf][1]));
            mx1 = fmaxf(mx1, fmaxf(sf[nf][2], sf[nf][3]));
        }
        mx0 = fmaxf(mx0, __shfl_xor_sync(0xffffffffu, mx0, 1));
        mx0 = fmaxf(mx0, __shfl_xor_sync(0xffffffffu, mx0, 2));
        mx1 = fmaxf(mx1, __shfl_xor_sync(0xffffffffu, mx1, 1));
        mx1 = fmaxf(mx1, __shfl_xor_sync(0xffffffffu, mx1, 2));

        const float mn0 = fmaxf(m0, mx0);
        const float mn1 = fmaxf(m1, mx1);
        const float c0 = __expf(m0 - mn0);
        const float c1 = __expf(m1 - mn1);
        m0 = mn0; m1 = mn1;

        float sum0 = 0.f, sum1 = 0.f;
#pragma unroll
        for (int nf = 0; nf < 8; nf++) {
            sf[nf][0] = __expf(sf[nf][0] - mn0);
            sf[nf][1] = __expf(sf[nf][1] - mn0);
            sf[nf][2] = __expf(sf[nf][2] - mn1);
            sf[nf][3] = __expf(sf[nf][3] - mn1);
            sum0 += sf[nf][0] + sf[nf][1];
            sum1 += sf[nf][2] + sf[nf][3];
        }
        sum0 += __shfl_xor_sync(0xffffffffu, sum0, 1);
        sum0 += __shfl_xor_sync(0xffffffffu, sum0, 2);
        sum1 += __shfl_xor_sync(0xffffffffu, sum1, 1);
        sum1 += __shfl_xor_sync(0xffffffffu, sum1, 2);
        l0 = l0 * c0 + sum0;
        l1 = l1 * c1 + sum1;

#pragma unroll
        for (int nf = 0; nf < 8; nf++) {
            o[nf][0] *= c0; o[nf][1] *= c0;
            o[nf][2] *= c1; o[nf][3] *= c1;
        }

        // ---- P -> bf16 hi/lo A-fragments ----
        uint32_t ph[4][4], pl[4][4];
#pragma unroll
        for (int kc = 0; kc < 4; kc++) {
            const int f0 = 2 * kc, f1 = 2 * kc + 1;
            float r00 = lo_of(sf[f0][0]);
            float r01 = lo_of(sf[f0][1]);
            float r02 = lo_of(sf[f0][2]);
            float r03 = lo_of(sf[f0][3]);
            float r10 = lo_of(sf[f1][0]);
            float r11 = lo_of(sf[f1][1]);
            float r12 = lo_of(sf[f1][2]);
            float r13 = lo_of(sf[f1][3]);
            ph[kc][0] = pkbf(sf[f0][1], sf[f0][0]);
            ph[kc][1] = pkbf(sf[f0][3], sf[f0][2]);
            ph[kc][2] = pkbf(sf[f1][1], sf[f1][0]);
            ph[kc][3] = pkbf(sf[f1][3], sf[f1][2]);
            pl[kc][0] = pkbf(r01, r00);
            pl[kc][1] = pkbf(r03, r02);
            pl[kc][2] = pkbf(r11, r10);
            pl[kc][3] = pkbf(r13, r12);
        }

        // ---- O += P V (Ph·Vh + Ph·Vl + Pl·Vh), V via ldmatrix.trans ----
#pragma unroll
        for (int nf = 0; nf < 8; nf++) {
#pragma unroll
            for (int kcb = 0; kcb < 4; kcb += 2) {
                uint32_t bh[4], bl[4];
                uint32_t off = (uint32_t)((kcb * 16 + (m4 & 1) * 8 + (m4 >> 1) * 16 + r8)
                               * (SROW * 2) + nf * 16);
                ldsm4t(bh, uVh + off);
                ldsm4t(bl, uVl + off);
                mma16816(o[nf], ph[kcb],     bh[0], bh[1]);
                mma16816(o[nf], ph[kcb],     bl[0], bl[1]);
                mma16816(o[nf], pl[kcb],     bh[0], bh[1]);
                mma16816(o[nf], ph[kcb + 1], bh[2], bh[3]);
                mma16816(o[nf], ph[kcb + 1], bl[2], bl[3]);
                mma16816(o[nf], pl[kcb + 1], bh[2], bh[3]);
            }
        }
    }

    // ---- epilogue ----
    const float inv0 = 1.f / l0;
    const float inv1 = 1.f / l1;
    float* ob = out + (size_t)batch * SEQ * HD;
#pragma unroll
    for (int nf = 0; nf < 8; nf++) {
        *(float2*)&ob[(size_t)qrow0 * HD + nf * 8 + 2 * tg] =
            make_float2(o[nf][0] * inv0, o[nf][1] * inv0);
        *(float2*)&ob[(size_t)qrow1 * HD + nf * 8 + 2 * tg] =
            make_float2(o[nf][2] * inv1, o[nf][3] * inv1);
    }
}

// ---------------------------------------------------------------------------
extern "C" void kernel_launch(void* const* d_in, const int* in_sizes, int n_in,
                              void* d_out, int out_size)
{
    const float* x  = (const float*)d_in[0];
    const float* Wq = (const float*)d_in[1];
    const float* Wk = (const float*)d_in[2];
    const float* Wv = (const float*)d_in[3];
    float* out = (float*)d_out;

    static bool attr_set = false;
    if (!attr_set) {
        cudaFuncSetAttribute(attn_kernel,
                             cudaFuncAttributeMaxDynamicSharedMemorySize,
                             ATTN_SMEM_BYTES);
        cudaFuncSetAttribute(qkv_tc_kernel,
                             cudaFuncAttributeMaxDynamicSharedMemorySize,
                             QKV_SMEM_BYTES);
        attr_set = true;
    }

    conv_w_kernel<<<1024, 192>>>(Wq, Wk, Wv);
    qkv_tc_kernel<<<MROWS / 128, 256, QKV_SMEM_BYTES>>>(x);
    attn_kernel<<<BATCH * 32, 128, ATTN_SMEM_BYTES>>>(out);
}

// round 9
// speedup vs baseline: 2.3796x; 1.0069x over previous
#include <cuda_runtime.h>
#include <cuda_bf16.h>
#include <cstdint>

// Problem constants
#define BATCH 8
#define SEQ   2048
#define EMB   1024
#define HD    64
#define MROWS (BATCH*SEQ)      // 16384
#define SCALE 0.03125f         // 1024^-0.5

// Scratch (device globals: no allocation allowed)
// Q pre-scaled by SCALE; all stored as bf16 hi + lo (hi+lo ~= fp32 value)
__device__ __nv_bfloat16 g_qh[MROWS*HD];
__device__ __nv_bfloat16 g_ql[MROWS*HD];
__device__ __nv_bfloat16 g_kh[MROWS*HD];
__device__ __nv_bfloat16 g_kl[MROWS*HD];
__device__ __nv_bfloat16 g_vh[MROWS*HD];
__device__ __nv_bfloat16 g_vl[MROWS*HD];
// Weights in B-operand layout [192][1024] K-major, bf16 hi/lo
__device__ __nv_bfloat16 g_Bh[192*1024];
__device__ __nv_bfloat16 g_Bl[192*1024];

// ---------------------------------------------------------------------------
// helpers
// ---------------------------------------------------------------------------
// pack: upper half <- bf16(hi_val), lower half <- bf16(lo_val)
__device__ __forceinline__ uint32_t pkbf(float hi_val, float lo_val) {
    uint32_t d;
    asm("cvt.rn.bf16x2.f32 %0, %1, %2;" : "=r"(d) : "f"(hi_val), "f"(lo_val));
    return d;
}
__device__ __forceinline__ uint32_t smem_u32(const void* p) {
    uint32_t a;
    asm("{ .reg .u64 t; cvta.to.shared.u64 t, %1; cvt.u32.u64 %0, t; }"
        : "=r"(a) : "l"(p));
    return a;
}
__device__ __forceinline__ void ldsm4(uint32_t* r, uint32_t addr) {
    asm volatile("ldmatrix.sync.aligned.m8n8.x4.shared.b16 {%0,%1,%2,%3}, [%4];"
        : "=r"(r[0]), "=r"(r[1]), "=r"(r[2]), "=r"(r[3]) : "r"(addr));
}
__device__ __forceinline__ void ldsm4t(uint32_t* r, uint32_t addr) {
    asm volatile("ldmatrix.sync.aligned.m8n8.x4.trans.shared.b16 {%0,%1,%2,%3}, [%4];"
        : "=r"(r[0]), "=r"(r[1]), "=r"(r[2]), "=r"(r[3]) : "r"(addr));
}
// NOTE: intentionally NOT volatile — register-only op; lets ptxas interleave
// the independent accumulator chains to hide HMMA latency.
__device__ __forceinline__ void mma16816(float* d, const uint32_t* a,
                                         uint32_t b0, uint32_t b1) {
    asm("mma.sync.aligned.m16n8k16.row.col.f32.bf16.bf16.f32 "
        "{%0,%1,%2,%3}, {%4,%5,%6,%7}, {%8,%9}, {%0,%1,%2,%3};"
        : "+f"(d[0]), "+f"(d[1]), "+f"(d[2]), "+f"(d[3])
        : "r"(a[0]), "r"(a[1]), "r"(a[2]), "r"(a[3]), "r"(b0), "r"(b1));
}
__device__ __forceinline__ float lo_of(float v) {
    return v - __bfloat162float(__float2bfloat16(v));
}

// ---------------------------------------------------------------------------
// Kernel 0: weight conversion -> [192][1024] K-major, bf16 hi/lo.
// grid = (16, 3), block = 256. smem transpose: coalesced reads AND writes.
// ---------------------------------------------------------------------------
__global__ void conv_w_kernel(const float* __restrict__ Wq,
                              const float* __restrict__ Wk,
                              const float* __restrict__ Wv)
{
    __shared__ float tile[64][65];
    const int kb  = blockIdx.x * 64;
    const int mat = blockIdx.y;
    const int tid = threadIdx.x;
    const float* W = (mat == 0) ? Wq : (mat == 1) ? Wk : Wv;

    // load 64k x 64n, coalesced over n
#pragma unroll
    for (int i = tid; i < 4096; i += 256) {
        int k = i >> 6, n = i & 63;
        tile[k][n] = W[(size_t)(kb + k) * 64 + n];
    }
    __syncthreads();
    // write transposed, coalesced over k
#pragma unroll
    for (int i = tid; i < 4096; i += 256) {
        int n = i >> 6, k = i & 63;
        float v = tile[k][n];
        __nv_bfloat16 h = __float2bfloat16(v);
        const size_t off = (size_t)(mat * 64 + n) * 1024 + kb + k;
        g_Bh[off] = h;
        g_Bl[off] = __float2bfloat16(v - __bfloat162float(h));
    }
}

// ---------------------------------------------------------------------------
// Kernel 1: QKV projection via mma.sync bf16 hi/lo split.
// grid = 128 (M tiles of 128), block = 256 (2x4 warp grid, 64Mx48N each).
// D[128x192] = Xh*Wh + Xh*Wl + Xl*Wh, K=1024 in BK=64 chunks, double-buffered.
// ---------------------------------------------------------------------------
#define QSTR 144                   // smem row stride bytes (72 bf16)
#define XH_OFF 0                   // elem offsets within one buffer
#define XL_OFF 9216                // 128*72
#define WH_OFF 18432
#define WL_OFF 32256               // 18432 + 192*72
#define QBUF_ELEMS 46080           // 32256 + 13824
#define QKV_SMEM_BYTES (2 * QBUF_ELEMS * 2)   // 184320

__global__ __launch_bounds__(256) void qkv_tc_kernel(const float* __restrict__ x)
{
    extern __shared__ __nv_bfloat16 qs[];
    const uint32_t uBase = smem_u32(qs);

    const int tid  = threadIdx.x;
    const int wid  = tid >> 5;
    const int lane = tid & 31;
    const int wm   = wid >> 2;       // 0..1 (M half)
    const int wn   = wid & 3;        // 0..3 (N quarter: 48 cols)
    const int m4   = lane >> 3;
    const int r8   = lane & 7;
    const int g    = lane >> 2;
    const int tg   = lane & 3;
    const int row0 = blockIdx.x * 128;

    // staging mapping
    const int xr  = tid >> 1;          // x row 0..127
    const int xc0 = (tid & 1) * 32;    // 32-elem half

    float acc[4][6][4] = {};
    float4 xv[8];
    uint4  wh6[6], wl6[6];

#define LOADX(c) do { \
    _Pragma("unroll") \
    for (int j = 0; j < 8; j++) \
        xv[j] = *(const float4*)&x[(size_t)(row0 + xr) * EMB + (c) * 64 + xc0 + j * 4]; \
    _Pragma("unroll") \
    for (int j = 0; j < 6; j++) { \
        int gi = tid + j * 256; \
        int rw = gi >> 3, sg = gi & 7; \
        wh6[j] = *(const uint4*)&g_Bh[rw * 1024 + (c) * 64 + sg * 8]; \
        wl6[j] = *(const uint4*)&g_Bl[rw * 1024 + (c) * 64 + sg * 8]; \
    } \
} while (0)

#define STOREB(b) do { \
    __nv_bfloat16* base = qs + (b) * QBUF_ELEMS; \
    _Pragma("unroll") \
    for (int j = 0; j < 8; j++) { \
        uint32_t h0 = pkbf(xv[j].y, xv[j].x); \
        uint32_t h1 = pkbf(xv[j].w, xv[j].z); \
        uint32_t l0 = pkbf(lo_of(xv[j].y), lo_of(xv[j].x)); \
        uint32_t l1 = pkbf(lo_of(xv[j].w), lo_of(xv[j].z)); \
        *(uint2*)(base + XH_OFF + xr * 72 + xc0 + j * 4) = make_uint2(h0, h1); \
        *(uint2*)(base + XL_OFF + xr * 72 + xc0 + j * 4) = make_uint2(l0, l1); \
    } \
    _Pragma("unroll") \
    for (int j = 0; j < 6; j++) { \
        int gi = tid + j * 256; \
        int rw = gi >> 3, sg = gi & 7; \
        *(uint4*)(base + WH_OFF + rw * 72 + sg * 8) = wh6[j]; \
        *(uint4*)(base + WL_OFF + rw * 72 + sg * 8) = wl6[j]; \
    } \
} while (0)

    // prologue
    LOADX(0);
    STOREB(0);

    for (int c = 0; c < 16; c++) {
        const int cur = c & 1;
        if (c < 15) LOADX(c + 1);
        __syncthreads();
        if (c < 15) STOREB(cur ^ 1);

        const uint32_t uB  = uBase + cur * (QBUF_ELEMS * 2);
        const uint32_t uXh = uB + XH_OFF * 2;
        const uint32_t uXl = uB + XL_OFF * 2;
        const uint32_t uWh = uB + WH_OFF * 2;
        const uint32_t uWl = uB + WL_OFF * 2;

#pragma unroll
        for (int kcb = 0; kcb < 4; kcb += 2) {
            uint32_t ah[4][2][4], al[4][2][4];
#pragma unroll
            for (int mf = 0; mf < 4; mf++)
#pragma unroll
                for (int kk = 0; kk < 2; kk++) {
                    uint32_t off = (uint32_t)((wm * 64 + mf * 16 + (m4 & 1) * 8 + r8) * QSTR
                                   + ((kcb + kk) * 16 + (m4 >> 1) * 8) * 2);
                    ldsm4(ah[mf][kk], uXh + off);
                    ldsm4(al[mf][kk], uXl + off);
                }
#pragma unroll
            for (int nf = 0; nf < 6; nf++) {
                uint32_t bh[4], bl[4];
                uint32_t off = (uint32_t)((wn * 48 + nf * 8 + r8) * QSTR
                               + (kcb * 16 + (m4 & 1) * 8 + (m4 >> 1) * 16) * 2);
                ldsm4(bh, uWh + off);
                ldsm4(bl, uWl + off);
#pragma unroll
                for (int mf = 0; mf < 4; mf++) {
                    mma16816(acc[mf][nf], ah[mf][0], bh[0], bh[1]);
                    mma16816(acc[mf][nf], ah[mf][0], bl[0], bl[1]);
                    mma16816(acc[mf][nf], al[mf][0], bh[0], bh[1]);
                    mma16816(acc[mf][nf], ah[mf][1], bh[2], bh[3]);
                    mma16816(acc[mf][nf], ah[mf][1], bl[2], bl[3]);
                    mma16816(acc[mf][nf], al[mf][1], bh[2], bh[3]);
                }
            }
        }
    }

    // epilogue: split accumulators into bf16 hi/lo, route to q/k/v
#pragma unroll
    for (int mf = 0; mf < 4; mf++) {
        const int r0 = row0 + wm * 64 + mf * 16 + g;
#pragma unroll
        for (int nf = 0; nf < 6; nf++) {
            const int n   = wn * 48 + nf * 8 + 2 * tg;
            const int mat = n >> 6;
            const int lc  = n & 63;
            __nv_bfloat16* oh = (mat == 0) ? g_qh : (mat == 1) ? g_kh : g_vh;
            __nv_bfloat16* ol = (mat == 0) ? g_ql : (mat == 1) ? g_kl : g_vl;
            const float sc = (mat == 0) ? SCALE : 1.0f;
            float v0 = acc[mf][nf][0] * sc, v1 = acc[mf][nf][1] * sc;
            float v2 = acc[mf][nf][2] * sc, v3 = acc[mf][nf][3] * sc;
            *(uint32_t*)&oh[(size_t)r0 * 64 + lc]       = pkbf(v1, v0);
            *(uint32_t*)&ol[(size_t)r0 * 64 + lc]       = pkbf(lo_of(v1), lo_of(v0));
            *(uint32_t*)&oh[(size_t)(r0 + 8) * 64 + lc] = pkbf(v3, v2);
            *(uint32_t*)&ol[(size_t)(r0 + 8) * 64 + lc] = pkbf(lo_of(v3), lo_of(v2));
        }
    }
#undef LOADX
#undef STOREB
}

// ---------------------------------------------------------------------------
// Kernel 2: causal flash attention on mma.sync bf16 (hi/lo split).
// 128 threads (4 warps x 16 q-rows), q-tile 64, k-tile 64.
// grid = 256 (batch x 32 q-tiles, heavy first).
// ---------------------------------------------------------------------------
#define SROW 72                       // smem row stride in bf16 elems
#define ATTN_SMEM_BYTES (6 * 64 * SROW * 2)   // Kh,Kl,Vh,Vl,Qh,Ql = 55296

__global__ __launch_bounds__(128) void attn_kernel(float* __restrict__ out)
{
    extern __shared__ __nv_bfloat16 smb[];
    __nv_bfloat16* sKh = smb;
    __nv_bfloat16* sKl = smb + 64 * SROW;
    __nv_bfloat16* sVh = smb + 2 * 64 * SROW;
    __nv_bfloat16* sVl = smb + 3 * 64 * SROW;
    __nv_bfloat16* sQh = smb + 4 * 64 * SROW;
    __nv_bfloat16* sQl = smb + 5 * 64 * SROW;

    const uint32_t uKh = smem_u32(sKh);
    const uint32_t uKl = smem_u32(sKl);
    const uint32_t uVh = smem_u32(sVh);
    const uint32_t uVl = smem_u32(sVl);
    const uint32_t uQh = smem_u32(sQh);
    const uint32_t uQl = smem_u32(sQl);

    const int bid   = blockIdx.x;
    const int batch = bid & 7;
    const int qt    = 31 - (bid >> 3);   // heavy q-tiles first
    const int q0    = qt * 64;

    const int tid  = threadIdx.x;
    const int wq   = tid >> 5;          // warp 0..3, q rows wq*16..+15
    const int lane = tid & 31;
    const int g    = lane >> 2;         // 0..7
    const int tg   = lane & 3;          // 0..3
    const int m4   = lane >> 3;         // ldmatrix matrix id 0..3
    const int r8   = lane & 7;

    const size_t bb = (size_t)batch * SEQ * HD;
    const __nv_bfloat16* gqh = g_qh + bb;
    const __nv_bfloat16* gql = g_ql + bb;
    const __nv_bfloat16* gkh = g_kh + bb;
    const __nv_bfloat16* gkl = g_kl + bb;
    const __nv_bfloat16* gvh = g_vh + bb;
    const __nv_bfloat16* gvl = g_vl + bb;

    // staging mapping: thread -> (row, 32-elem half-row)
    const int srow = tid >> 1;
    const int scol = (tid & 1) * 32;

    // ---- stage Q, build Q fragments (once) ----
    {
        const uint4* sh = (const uint4*)(gqh + (size_t)(q0 + srow) * HD + scol);
        const uint4* sl = (const uint4*)(gql + (size_t)(q0 + srow) * HD + scol);
        uint4 th[4], tl[4];
#pragma unroll
        for (int j = 0; j < 4; j++) { th[j] = sh[j]; tl[j] = sl[j]; }
#pragma unroll
        for (int j = 0; j < 4; j++) {
            *(uint4*)(sQh + srow * SROW + scol + 8 * j) = th[j];
            *(uint4*)(sQl + srow * SROW + scol + 8 * j) = tl[j];
        }
    }
    __syncthreads();

    uint32_t qh[4][4], ql[4][4];
    {
        const int qrow = wq * 16 + ((m4 & 1) << 3) + r8;
#pragma unroll
        for (int kc = 0; kc < 4; kc++) {
            uint32_t off = (uint32_t)(qrow * (SROW * 2) + (kc * 16 + (m4 >> 1) * 8) * 2);
            ldsm4(qh[kc], uQh + off);
            ldsm4(ql[kc], uQl + off);
        }
    }

    float o[8][4] = {};
    float m0 = -1e30f, m1 = -1e30f;
    float l0 = 0.f, l1 = 0.f;
    const int qrow0 = q0 + wq * 16 + g;
    const int qrow1 = qrow0 + 8;

    for (int kt = 0; kt <= qt; kt++) {
        const int k0 = kt * 64;

        // ---- stage K/V (prefetch into regs, 2 syncs) ----
        uint4 pf[16];
        {
            const uint4* s0 = (const uint4*)(gkh + (size_t)(k0 + srow) * HD + scol);
            const uint4* s1 = (const uint4*)(gkl + (size_t)(k0 + srow) * HD + scol);
            const uint4* s2 = (const uint4*)(gvh + (size_t)(k0 + srow) * HD + scol);
            const uint4* s3 = (const uint4*)(gvl + (size_t)(k0 + srow) * HD + scol);
#pragma unroll
            for (int j = 0; j < 4; j++) {
                pf[j]      = s0[j];
                pf[4 + j]  = s1[j];
                pf[8 + j]  = s2[j];
                pf[12 + j] = s3[j];
            }
        }
        __syncthreads();   // prior LDSM reads done
#pragma unroll
        for (int j = 0; j < 4; j++) {
            *(uint4*)(sKh + srow * SROW + scol + 8 * j) = pf[j];
            *(uint4*)(sKl + srow * SROW + scol + 8 * j) = pf[4 + j];
            *(uint4*)(sVh + srow * SROW + scol + 8 * j) = pf[8 + j];
            *(uint4*)(sVl + srow * SROW + scol + 8 * j) = pf[12 + j];
        }
        __syncthreads();   // tiles visible

        // ---- S = Q K^T (bf16 split: Qh·Kh + Qh·Kl + Ql·Kh) ----
        float sf[8][4];
#pragma unroll
        for (int nf = 0; nf < 8; nf++) {
            sf[nf][0] = sf[nf][1] = sf[nf][2] = sf[nf][3] = 0.f;
#pragma unroll
            for (int kcb = 0; kcb < 4; kcb += 2) {
                uint32_t bh[4], bl[4];
                uint32_t off = (uint32_t)((nf * 8 + r8) * (SROW * 2) +
                               (kcb * 16 + (m4 & 1) * 8 + (m4 >> 1) * 16) * 2);
                ldsm4(bh, uKh + off);
                ldsm4(bl, uKl + off);
                mma16816(sf[nf], qh[kcb],     bh[0], bh[1]);
                mma16816(sf[nf], qh[kcb],     bl[0], bl[1]);
                mma16816(sf[nf], ql[kcb],     bh[0], bh[1]);
                mma16816(sf[nf], qh[kcb + 1], bh[2], bh[3]);
                mma16816(sf[nf], qh[kcb + 1], bl[2], bl[3]);
                mma16816(sf[nf], ql[kcb + 1], bh[2], bh[3]);
            }
        }

        // ---- causal mask (diagonal tile) ----
        if (kt == qt) {
#pragma unroll
            for (int nf = 0; nf < 8; nf++) {
                const int col = k0 + nf * 8 + 2 * tg;
                if (col     > qrow0) sf[nf][0] = -1e30f;
                if (col + 1 > qrow0) sf[nf][1] = -1e30f;
                if (col     > qrow1) sf[nf][2] = -1e30f;
                if (col + 1 > qrow1) sf[nf][3] = -1e30f;
            }
        }

        // ---- online softmax (rows g, g+8; 4-lane shfl groups) ----
        float mx0 = -1e30f, mx1 = -1e30f;
#pragma unroll
        for (int nf = 0; nf < 8; nf++) {
            mx0 = fmaxf(mx0, fmaxf(sf[nf][0], sf[nf][1]));
            mx1 = fmaxf(mx1, fmaxf(sf[nf][2], sf[nf][3]));
        }
        mx0 = fmaxf(mx0, __shfl_xor_sync(0xffffffffu, mx0, 1));
        mx0 = fmaxf(mx0, __shfl_xor_sync(0xffffffffu, mx0, 2));
        mx1 = fmaxf(mx1, __shfl_xor_sync(0xffffffffu, mx1, 1));
        mx1 = fmaxf(mx1, __shfl_xor_sync(0xffffffffu, mx1, 2));

        const float mn0 = fmaxf(m0, mx0);
        const float mn1 = fmaxf(m1, mx1);
        const float c0 = __expf(m0 - mn0);
        const float c1 = __expf(m1 - mn1);
        m0 = mn0; m1 = mn1;

        float sum0 = 0.f, sum1 = 0.f;
#pragma unroll
        for (int nf = 0; nf < 8; nf++) {
            sf[nf][0] = __expf(sf[nf][0] - mn0);
            sf[nf][1] = __expf(sf[nf][1] - mn0);
            sf[nf][2] = __expf(sf[nf][2] - mn1);
            sf[nf][3] = __expf(sf[nf][3] - mn1);
            sum0 += sf[nf][0] + sf[nf][1];
            sum1 += sf[nf][2] + sf[nf][3];
        }
        sum0 += __shfl_xor_sync(0xffffffffu, sum0, 1);
        sum0 += __shfl_xor_sync(0xffffffffu, sum0, 2);
        sum1 += __shfl_xor_sync(0xffffffffu, sum1, 1);
        sum1 += __shfl_xor_sync(0xffffffffu, sum1, 2);
        l0 = l0 * c0 + sum0;
        l1 = l1 * c1 + sum1;

#pragma unroll
        for (int nf = 0; nf < 8; nf++) {
            o[nf][0] *= c0; o[nf][1] *= c0;
            o[nf][2] *= c1; o[nf][3] *= c1;
        }

        // ---- P -> bf16 hi/lo A-fragments ----
        uint32_t ph[4][4], pl[4][4];
#pragma unroll
        for (int kc = 0; kc < 4; kc++) {
            const int f0 = 2 * kc, f1 = 2 * kc + 1;
            float r00 = lo_of(sf[f0][0]);
            float r01 = lo_of(sf[f0][1]);
            float r02 = lo_of(sf[f0][2]);
            float r03 = lo_of(sf[f0][3]);
            float r10 = lo_of(sf[f1][0]);
            float r11 = lo_of(sf[f1][1]);
            float r12 = lo_of(sf[f1][2]);
            float r13 = lo_of(sf[f1][3]);
            ph[kc][0] = pkbf(sf[f0][1], sf[f0][0]);
            ph[kc][1] = pkbf(sf[f0][3], sf[f0][2]);
            ph[kc][2] = pkbf(sf[f1][1], sf[f1][0]);
            ph[kc][3] = pkbf(sf[f1][3], sf[f1][2]);
            pl[kc][0] = pkbf(r01, r00);
            pl[kc][1] = pkbf(r03, r02);
            pl[kc][2] = pkbf(r11, r10);
            pl[kc][3] = pkbf(r13, r12);
        }

        // ---- O += P V (Ph·Vh + Ph·Vl + Pl·Vh), V via ldmatrix.trans ----
#pragma unroll
        for (int nf = 0; nf < 8; nf++) {
#pragma unroll
            for (int kcb = 0; kcb < 4; kcb += 2) {
                uint32_t bh[4], bl[4];
                uint32_t off = (uint32_t)((kcb * 16 + (m4 & 1) * 8 + (m4 >> 1) * 16 + r8)
                               * (SROW * 2) + nf * 16);
                ldsm4t(bh, uVh + off);
                ldsm4t(bl, uVl + off);
                mma16816(o[nf], ph[kcb],     bh[0], bh[1]);
                mma16816(o[nf], ph[kcb],     bl[0], bl[1]);
                mma16816(o[nf], pl[kcb],     bh[0], bh[1]);
                mma16816(o[nf], ph[kcb + 1], bh[2], bh[3]);
                mma16816(o[nf], ph[kcb + 1], bl[2], bl[3]);
                mma16816(o[nf], pl[kcb + 1], bh[2], bh[3]);
            }
        }
    }

    // ---- epilogue ----
    const float inv0 = 1.f / l0;
    const float inv1 = 1.f / l1;
    float* ob = out + (size_t)batch * SEQ * HD;
#pragma unroll
    for (int nf = 0; nf < 8; nf++) {
        *(float2*)&ob[(size_t)qrow0 * HD + nf * 8 + 2 * tg] =
            make_float2(o[nf][0] * inv0, o[nf][1] * inv0);
        *(float2*)&ob[(size_t)qrow1 * HD + nf * 8 + 2 * tg] =
            make_float2(o[nf][2] * inv1, o[nf][3] * inv1);
    }
}

// ---------------------------------------------------------------------------
extern "C" void kernel_launch(void* const* d_in, const int* in_sizes, int n_in,
                              void* d_out, int out_size)
{
    const float* x  = (const float*)d_in[0];
    const float* Wq = (const float*)d_in[1];
    const float* Wk = (const float*)d_in[2];
    const float* Wv = (const float*)d_in[3];
    float* out = (float*)d_out;

    static bool attr_set = false;
    if (!attr_set) {
        cudaFuncSetAttribute(attn_kernel,
                             cudaFuncAttributeMaxDynamicSharedMemorySize,
                             ATTN_SMEM_BYTES);
        cudaFuncSetAttribute(qkv_tc_kernel,
                             cudaFuncAttributeMaxDynamicSharedMemorySize,
                             QKV_SMEM_BYTES);
        attr_set = true;
    }

    conv_w_kernel<<<dim3(16, 3), 256>>>(Wq, Wk, Wv);
    qkv_tc_kernel<<<MROWS / 128, 256, QKV_SMEM_BYTES>>>(x);
    attn_kernel<<<BATCH * 32, 128, ATTN_SMEM_BYTES>>>(out);
}

// round 10
// speedup vs baseline: 3.0826x; 1.2954x over previous
#include <cuda_runtime.h>
#include <cuda_fp16.h>
#include <cstdint>

// Problem constants
#define BATCH 8
#define SEQ   2048
#define EMB   1024
#define HD    64
#define MROWS (BATCH*SEQ)      // 16384
#define SCALE 0.03125f         // 1024^-0.5

// Scratch (device globals: no allocation allowed)
// q: fp16, pre-scaled by SCALE. k,v: fp16 hi + lo (hi+lo ~= fp32 value).
__device__ __half g_q [MROWS*HD];
__device__ __half g_kh[MROWS*HD];
__device__ __half g_kl[MROWS*HD];
__device__ __half g_vh[MROWS*HD];
__device__ __half g_vl[MROWS*HD];
// Weights in B-operand layout [192][1024] K-major, fp16 hi/lo
__device__ __half g_Bh[192*1024];
__device__ __half g_Bl[192*1024];

// ---------------------------------------------------------------------------
// helpers
// ---------------------------------------------------------------------------
// pack: upper half <- f16(hi_val), lower half <- f16(lo_val)
__device__ __forceinline__ uint32_t pkh(float hi_val, float lo_val) {
    uint32_t d;
    asm("cvt.rn.f16x2.f32 %0, %1, %2;" : "=r"(d) : "f"(hi_val), "f"(lo_val));
    return d;
}
__device__ __forceinline__ uint32_t smem_u32(const void* p) {
    uint32_t a;
    asm("{ .reg .u64 t; cvta.to.shared.u64 t, %1; cvt.u32.u64 %0, t; }"
        : "=r"(a) : "l"(p));
    return a;
}
__device__ __forceinline__ void ldsm4(uint32_t* r, uint32_t addr) {
    asm volatile("ldmatrix.sync.aligned.m8n8.x4.shared.b16 {%0,%1,%2,%3}, [%4];"
        : "=r"(r[0]), "=r"(r[1]), "=r"(r[2]), "=r"(r[3]) : "r"(addr));
}
__device__ __forceinline__ void ldsm4t(uint32_t* r, uint32_t addr) {
    asm volatile("ldmatrix.sync.aligned.m8n8.x4.trans.shared.b16 {%0,%1,%2,%3}, [%4];"
        : "=r"(r[0]), "=r"(r[1]), "=r"(r[2]), "=r"(r[3]) : "r"(addr));
}
__device__ __forceinline__ void mma16816(float* d, const uint32_t* a,
                                         uint32_t b0, uint32_t b1) {
    asm("mma.sync.aligned.m16n8k16.row.col.f32.f16.f16.f32 "
        "{%0,%1,%2,%3}, {%4,%5,%6,%7}, {%8,%9}, {%0,%1,%2,%3};"
        : "+f"(d[0]), "+f"(d[1]), "+f"(d[2]), "+f"(d[3])
        : "r"(a[0]), "r"(a[1]), "r"(a[2]), "r"(a[3]), "r"(b0), "r"(b1));
}
__device__ __forceinline__ float lo_of(float v) {
    return v - __half2float(__float2half(v));
}

// ---------------------------------------------------------------------------
// Kernel 0: weight conversion -> [192][1024] K-major, fp16 hi/lo.
// grid = (16, 3), block = 256. smem transpose: coalesced reads AND writes.
// ---------------------------------------------------------------------------
__global__ void conv_w_kernel(const float* __restrict__ Wq,
                              const float* __restrict__ Wk,
                              const float* __restrict__ Wv)
{
    __shared__ float tile[64][65];
    const int kb  = blockIdx.x * 64;
    const int mat = blockIdx.y;
    const int tid = threadIdx.x;
    const float* W = (mat == 0) ? Wq : (mat == 1) ? Wk : Wv;

#pragma unroll
    for (int i = tid; i < 4096; i += 256) {
        int k = i >> 6, n = i & 63;
        tile[k][n] = W[(size_t)(kb + k) * 64 + n];
    }
    __syncthreads();
#pragma unroll
    for (int i = tid; i < 4096; i += 256) {
        int n = i >> 6, k = i & 63;
        float v = tile[k][n];
        __half h = __float2half(v);
        const size_t off = (size_t)(mat * 64 + n) * 1024 + kb + k;
        g_Bh[off] = h;
        g_Bl[off] = __float2half(v - __half2float(h));
    }
}

// ---------------------------------------------------------------------------
// Kernel 1: QKV projection via mma.sync fp16 2-product split.
// grid = 128 (M tiles of 128), block = 256 (2x4 warp grid, 64Mx48N each).
// D[128x192] = Xh*Wh + Xh*Wl, K=1024 in BK=64 chunks, double-buffered.
// ---------------------------------------------------------------------------
#define QSTR 144                   // smem row stride bytes (72 fp16)
#define XH_OFF 0                   // elem offsets within one buffer
#define WH_OFF 9216                // 128*72
#define WL_OFF 23040               // 9216 + 192*72
#define QBUF_ELEMS 36864           // 23040 + 13824
#define QKV_SMEM_BYTES (2 * QBUF_ELEMS * 2)   // 147456

__global__ __launch_bounds__(256) void qkv_tc_kernel(const float* __restrict__ x)
{
    extern __shared__ __half qs[];
    const uint32_t uBase = smem_u32(qs);

    const int tid  = threadIdx.x;
    const int wid  = tid >> 5;
    const int lane = tid & 31;
    const int wm   = wid >> 2;       // 0..1 (M half)
    const int wn   = wid & 3;        // 0..3 (N quarter: 48 cols)
    const int m4   = lane >> 3;
    const int r8   = lane & 7;
    const int g    = lane >> 2;
    const int tg   = lane & 3;
    const int row0 = blockIdx.x * 128;

    // staging mapping
    const int xr  = tid >> 1;          // x row 0..127
    const int xc0 = (tid & 1) * 32;    // 32-elem half

    float acc[4][6][4] = {};
    float4 xv[8];
    uint4  wh6[6], wl6[6];

#define LOADX(c) do { \
    _Pragma("unroll") \
    for (int j = 0; j < 8; j++) \
        xv[j] = *(const float4*)&x[(size_t)(row0 + xr) * EMB + (c) * 64 + xc0 + j * 4]; \
    _Pragma("unroll") \
    for (int j = 0; j < 6; j++) { \
        int gi = tid + j * 256; \
        int rw = gi >> 3, sg = gi & 7; \
        wh6[j] = *(const uint4*)&g_Bh[rw * 1024 + (c) * 64 + sg * 8]; \
        wl6[j] = *(const uint4*)&g_Bl[rw * 1024 + (c) * 64 + sg * 8]; \
    } \
} while (0)

#define STOREB(b) do { \
    __half* base = qs + (b) * QBUF_ELEMS; \
    _Pragma("unroll") \
    for (int j = 0; j < 8; j++) { \
        uint32_t h0 = pkh(xv[j].y, xv[j].x); \
        uint32_t h1 = pkh(xv[j].w, xv[j].z); \
        *(uint2*)(base + XH_OFF + xr * 72 + xc0 + j * 4) = make_uint2(h0, h1); \
    } \
    _Pragma("unroll") \
    for (int j = 0; j < 6; j++) { \
        int gi = tid + j * 256; \
        int rw = gi >> 3, sg = gi & 7; \
        *(uint4*)(base + WH_OFF + rw * 72 + sg * 8) = wh6[j]; \
        *(uint4*)(base + WL_OFF + rw * 72 + sg * 8) = wl6[j]; \
    } \
} while (0)

    // prologue
    LOADX(0);
    STOREB(0);

    for (int c = 0; c < 16; c++) {
        const int cur = c & 1;
        if (c < 15) LOADX(c + 1);
        __syncthreads();
        if (c < 15) STOREB(cur ^ 1);

        const uint32_t uB  = uBase + cur * (QBUF_ELEMS * 2);
        const uint32_t uXh = uB + XH_OFF * 2;
        const uint32_t uWh = uB + WH_OFF * 2;
        const uint32_t uWl = uB + WL_OFF * 2;

#pragma unroll
        for (int kcb = 0; kcb < 4; kcb += 2) {
            uint32_t ah[4][2][4];
#pragma unroll
            for (int mf = 0; mf < 4; mf++)
#pragma unroll
                for (int kk = 0; kk < 2; kk++) {
                    uint32_t off = (uint32_t)((wm * 64 + mf * 16 + (m4 & 1) * 8 + r8) * QSTR
                                   + ((kcb + kk) * 16 + (m4 >> 1) * 8) * 2);
                    ldsm4(ah[mf][kk], uXh + off);
                }
#pragma unroll
            for (int nf = 0; nf < 6; nf++) {
                uint32_t bh[4], bl[4];
                uint32_t off = (uint32_t)((wn * 48 + nf * 8 + r8) * QSTR
                               + (kcb * 16 + (m4 & 1) * 8 + (m4 >> 1) * 16) * 2);
                ldsm4(bh, uWh + off);
                ldsm4(bl, uWl + off);
#pragma unroll
                for (int mf = 0; mf < 4; mf++) {
                    mma16816(acc[mf][nf], ah[mf][0], bh[0], bh[1]);
                    mma16816(acc[mf][nf], ah[mf][0], bl[0], bl[1]);
                    mma16816(acc[mf][nf], ah[mf][1], bh[2], bh[3]);
                    mma16816(acc[mf][nf], ah[mf][1], bl[2], bl[3]);
                }
            }
        }
    }

    // epilogue: q -> fp16 (scaled); k,v -> fp16 hi/lo
#pragma unroll
    for (int mf = 0; mf < 4; mf++) {
        const int r0 = row0 + wm * 64 + mf * 16 + g;
#pragma unroll
        for (int nf = 0; nf < 6; nf++) {
            const int n   = wn * 48 + nf * 8 + 2 * tg;
            const int mat = n >> 6;
            const int lc  = n & 63;
            float v0 = acc[mf][nf][0], v1 = acc[mf][nf][1];
            float v2 = acc[mf][nf][2], v3 = acc[mf][nf][3];
            if (mat == 0) {
                v0 *= SCALE; v1 *= SCALE; v2 *= SCALE; v3 *= SCALE;
                *(uint32_t*)&g_q[(size_t)r0 * 64 + lc]       = pkh(v1, v0);
                *(uint32_t*)&g_q[(size_t)(r0 + 8) * 64 + lc] = pkh(v3, v2);
            } else {
                __half* oh = (mat == 1) ? g_kh : g_vh;
                __half* ol = (mat == 1) ? g_kl : g_vl;
                *(uint32_t*)&oh[(size_t)r0 * 64 + lc]       = pkh(v1, v0);
                *(uint32_t*)&ol[(size_t)r0 * 64 + lc]       = pkh(lo_of(v1), lo_of(v0));
                *(uint32_t*)&oh[(size_t)(r0 + 8) * 64 + lc] = pkh(v3, v2);
                *(uint32_t*)&ol[(size_t)(r0 + 8) * 64 + lc] = pkh(lo_of(v3), lo_of(v2));
            }
        }
    }
#undef LOADX
#undef STOREB
}

// ---------------------------------------------------------------------------
// Kernel 2: causal flash attention on mma.sync fp16 2-product split.
// 128 threads (4 warps x 16 q-rows), q-tile 64, k-tile 64.
// grid = 256 (batch x 32 q-tiles, heavy first).
// ---------------------------------------------------------------------------
#define SROW 72                       // smem row stride in fp16 elems
#define ATTN_SMEM_BYTES (5 * 64 * SROW * 2)   // Kh,Kl,Vh,Vl,Q = 46080

__global__ __launch_bounds__(128) void attn_kernel(float* __restrict__ out)
{
    extern __shared__ __half smh[];
    __half* sKh = smh;
    __half* sKl = smh + 64 * SROW;
    __half* sVh = smh + 2 * 64 * SROW;
    __half* sVl = smh + 3 * 64 * SROW;
    __half* sQ  = smh + 4 * 64 * SROW;

    const uint32_t uKh = smem_u32(sKh);
    const uint32_t uKl = smem_u32(sKl);
    const uint32_t uVh = smem_u32(sVh);
    const uint32_t uVl = smem_u32(sVl);
    const uint32_t uQ  = smem_u32(sQ);

    const int bid   = blockIdx.x;
    const int batch = bid & 7;
    const int qt    = 31 - (bid >> 3);   // heavy q-tiles first
    const int q0    = qt * 64;

    const int tid  = threadIdx.x;
    const int wq   = tid >> 5;          // warp 0..3, q rows wq*16..+15
    const int lane = tid & 31;
    const int g    = lane >> 2;         // 0..7
    const int tg   = lane & 3;          // 0..3
    const int m4   = lane >> 3;         // ldmatrix matrix id 0..3
    const int r8   = lane & 7;

    const size_t bb = (size_t)batch * SEQ * HD;
    const __half* gq  = g_q  + bb;
    const __half* gkh = g_kh + bb;
    const __half* gkl = g_kl + bb;
    const __half* gvh = g_vh + bb;
    const __half* gvl = g_vl + bb;

    // staging mapping: thread -> (row, 32-elem half-row)
    const int srow = tid >> 1;
    const int scol = (tid & 1) * 32;

    // ---- stage Q, build Q fragments (once) ----
    {
        const uint4* sq = (const uint4*)(gq + (size_t)(q0 + srow) * HD + scol);
        uint4 t[4];
#pragma unroll
        for (int j = 0; j < 4; j++) t[j] = sq[j];
#pragma unroll
        for (int j = 0; j < 4; j++)
            *(uint4*)(sQ + srow * SROW + scol + 8 * j) = t[j];
    }
    __syncthreads();

    uint32_t qh[4][4];
    {
        const int qrow = wq * 16 + ((m4 & 1) << 3) + r8;
#pragma unroll
        for (int kc = 0; kc < 4; kc++) {
            uint32_t off = (uint32_t)(qrow * (SROW * 2) + (kc * 16 + (m4 >> 1) * 8) * 2);
            ldsm4(qh[kc], uQ + off);
        }
    }

    float o[8][4] = {};
    float m0 = -1e30f, m1 = -1e30f;
    float l0 = 0.f, l1 = 0.f;
    const int qrow0 = q0 + wq * 16 + g;
    const int qrow1 = qrow0 + 8;

    for (int kt = 0; kt <= qt; kt++) {
        const int k0 = kt * 64;

        // ---- stage K/V (prefetch into regs, 2 syncs) ----
        uint4 pf[16];
        {
            const uint4* s0 = (const uint4*)(gkh + (size_t)(k0 + srow) * HD + scol);
            const uint4* s1 = (const uint4*)(gkl + (size_t)(k0 + srow) * HD + scol);
            const uint4* s2 = (const uint4*)(gvh + (size_t)(k0 + srow) * HD + scol);
            const uint4* s3 = (const uint4*)(gvl + (size_t)(k0 + srow) * HD + scol);
#pragma unroll
            for (int j = 0; j < 4; j++) {
                pf[j]      = s0[j];
                pf[4 + j]  = s1[j];
                pf[8 + j]  = s2[j];
                pf[12 + j] = s3[j];
            }
        }
        __syncthreads();   // prior LDSM reads done
#pragma unroll
        for (int j = 0; j < 4; j++) {
            *(uint4*)(sKh + srow * SROW + scol + 8 * j) = pf[j];
            *(uint4*)(sKl + srow * SROW + scol + 8 * j) = pf[4 + j];
            *(uint4*)(sVh + srow * SROW + scol + 8 * j) = pf[8 + j];
            *(uint4*)(sVl + srow * SROW + scol + 8 * j) = pf[12 + j];
        }
        __syncthreads();   // tiles visible

        // ---- S = Q K^T  (fp16 split: q·Kh + q·Kl) ----
        float sf[8][4];
#pragma unroll
        for (int nf = 0; nf < 8; nf++) {
            sf[nf][0] = sf[nf][1] = sf[nf][2] = sf[nf][3] = 0.f;
#pragma unroll
            for (int kcb = 0; kcb < 4; kcb += 2) {
                uint32_t bh[4], bl[4];
                uint32_t off = (uint32_t)((nf * 8 + r8) * (SROW * 2) +
                               (kcb * 16 + (m4 & 1) * 8 + (m4 >> 1) * 16) * 2);
                ldsm4(bh, uKh + off);
                ldsm4(bl, uKl + off);
                mma16816(sf[nf], qh[kcb],     bh[0], bh[1]);
                mma16816(sf[nf], qh[kcb],     bl[0], bl[1]);
                mma16816(sf[nf], qh[kcb + 1], bh[2], bh[3]);
                mma16816(sf[nf], qh[kcb + 1], bl[2], bl[3]);
            }
        }

        // ---- causal mask (diagonal tile) ----
        if (kt == qt) {
#pragma unroll
            for (int nf = 0; nf < 8; nf++) {
                const int col = k0 + nf * 8 + 2 * tg;
                if (col     > qrow0) sf[nf][0] = -1e30f;
                if (col + 1 > qrow0) sf[nf][1] = -1e30f;
                if (col     > qrow1) sf[nf][2] = -1e30f;
                if (col + 1 > qrow1) sf[nf][3] = -1e30f;
            }
        }

        // ---- online softmax (rows g, g+8; 4-lane shfl groups) ----
        float mx0 = -1e30f, mx1 = -1e30f;
#pragma unroll
        for (int nf = 0; nf < 8; nf++) {
            mx0 = fmaxf(mx0, fmaxf(sf[nf][0], sf[nf][1]));
            mx1 = fmaxf(mx1, fmaxf(sf[nf][2], sf[nf][3]));
        }
        mx0 = fmaxf(mx0, __shfl_xor_sync(0xffffffffu, mx0, 1));
        mx0 = fmaxf(mx0, __shfl_xor_sync(0xffffffffu, mx0, 2));
        mx1 = fmaxf(mx1, __shfl_xor_sync(0xffffffffu, mx1, 1));
        mx1 = fmaxf(mx1, __shfl_xor_sync(0xffffffffu, mx1, 2));

        const float mn0 = fmaxf(m0, mx0);
        const float mn1 = fmaxf(m1, mx1);
        const float c0 = __expf(m0 - mn0);
        const float c1 = __expf(m1 - mn1);
        m0 = mn0; m1 = mn1;

        float sum0 = 0.f, sum1 = 0.f;
#pragma unroll
        for (int nf = 0; nf < 8; nf++) {
            sf[nf][0] = __expf(sf[nf][0] - mn0);
            sf[nf][1] = __expf(sf[nf][1] - mn0);
            sf[nf][2] = __expf(sf[nf][2] - mn1);
            sf[nf][3] = __expf(sf[nf][3] - mn1);
            sum0 += sf[nf][0] + sf[nf][1];
            sum1 += sf[nf][2] + sf[nf][3];
        }
        sum0 += __shfl_xor_sync(0xffffffffu, sum0, 1);
        sum0 += __shfl_xor_sync(0xffffffffu, sum0, 2);
        sum1 += __shfl_xor_sync(0xffffffffu, sum1, 1);
        sum1 += __shfl_xor_sync(0xffffffffu, sum1, 2);
        l0 = l0 * c0 + sum0;
        l1 = l1 * c1 + sum1;

#pragma unroll
        for (int nf = 0; nf < 8; nf++) {
            o[nf][0] *= c0; o[nf][1] *= c0;
            o[nf][2] *= c1; o[nf][3] *= c1;
        }

        // ---- P -> fp16 A-fragments (hi only) ----
        uint32_t ph[4][4];
#pragma unroll
        for (int kc = 0; kc < 4; kc++) {
            const int f0 = 2 * kc, f1 = 2 * kc + 1;
            ph[kc][0] = pkh(sf[f0][1], sf[f0][0]);
            ph[kc][1] = pkh(sf[f0][3], sf[f0][2]);
            ph[kc][2] = pkh(sf[f1][1], sf[f1][0]);
            ph[kc][3] = pkh(sf[f1][3], sf[f1][2]);
        }

        // ---- O += P V  (P·Vh + P·Vl), V via ldmatrix.trans ----
#pragma unroll
        for (int nf = 0; nf < 8; nf++) {
#pragma unroll
            for (int kcb = 0; kcb < 4; kcb += 2) {
                uint32_t bh[4], bl[4];
                uint32_t off = (uint32_t)((kcb * 16 + (m4 & 1) * 8 + (m4 >> 1) * 16 + r8)
                               * (SROW * 2) + nf * 16);
                ldsm4t(bh, uVh + off);
                ldsm4t(bl, uVl + off);
                mma16816(o[nf], ph[kcb],     bh[0], bh[1]);
                mma16816(o[nf], ph[kcb],     bl[0], bl[1]);
                mma16816(o[nf], ph[kcb + 1], bh[2], bh[3]);
                mma16816(o[nf], ph[kcb + 1], bl[2], bl[3]);
            }
        }
    }

    // ---- epilogue ----
    const float inv0 = 1.f / l0;
    const float inv1 = 1.f / l1;
    float* ob = out + (size_t)batch * SEQ * HD;
#pragma unroll
    for (int nf = 0; nf < 8; nf++) {
        *(float2*)&ob[(size_t)qrow0 * HD + nf * 8 + 2 * tg] =
            make_float2(o[nf][0] * inv0, o[nf][1] * inv0);
        *(float2*)&ob[(size_t)qrow1 * HD + nf * 8 + 2 * tg] =
            make_float2(o[nf][2] * inv1, o[nf][3] * inv1);
    }
}

// ---------------------------------------------------------------------------
extern "C" void kernel_launch(void* const* d_in, const int* in_sizes, int n_in,
                              void* d_out, int out_size)
{
    const float* x  = (const float*)d_in[0];
    const float* Wq = (const float*)d_in[1];
    const float* Wk = (const float*)d_in[2];
    const float* Wv = (const float*)d_in[3];
    float* out = (float*)d_out;

    static bool attr_set = false;
    if (!attr_set) {
        cudaFuncSetAttribute(attn_kernel,
                             cudaFuncAttributeMaxDynamicSharedMemorySize,
                             ATTN_SMEM_BYTES);
        cudaFuncSetAttribute(qkv_tc_kernel,
                             cudaFuncAttributeMaxDynamicSharedMemorySize,
                             QKV_SMEM_BYTES);
        attr_set = true;
    }

    conv_w_kernel<<<dim3(16, 3), 256>>>(Wq, Wk, Wv);
    qkv_tc_kernel<<<MROWS / 128, 256, QKV_SMEM_BYTES>>>(x);
    attn_kernel<<<BATCH * 32, 128, ATTN_SMEM_BYTES>>>(out);
}

// round 11
// speedup vs baseline: 3.9448x; 1.2797x over previous
#include <cuda_runtime.h>
#include <cuda_fp16.h>
#include <cstdint>

// Problem constants
#define BATCH 8
#define SEQ   2048
#define EMB   1024
#define HD    64
#define MROWS (BATCH*SEQ)      // 16384
#define SCALE 0.03125f         // 1024^-0.5

// Scratch (device globals: no allocation allowed)
// q: fp16, pre-scaled by SCALE. k,v: fp16 hi + lo (hi+lo ~= fp32 value).
__device__ __half g_q [MROWS*HD];
__device__ __half g_kh[MROWS*HD];
__device__ __half g_kl[MROWS*HD];
__device__ __half g_vh[MROWS*HD];
__device__ __half g_vl[MROWS*HD];
// Weights in B-operand layout [192][1024] K-major, fp16
__device__ __half g_Bh[192*1024];

// ---------------------------------------------------------------------------
// helpers
// ---------------------------------------------------------------------------
// pack: upper half <- f16(hi_val), lower half <- f16(lo_val)
__device__ __forceinline__ uint32_t pkh(float hi_val, float lo_val) {
    uint32_t d;
    asm("cvt.rn.f16x2.f32 %0, %1, %2;" : "=r"(d) : "f"(hi_val), "f"(lo_val));
    return d;
}
__device__ __forceinline__ uint32_t smem_u32(const void* p) {
    uint32_t a;
    asm("{ .reg .u64 t; cvta.to.shared.u64 t, %1; cvt.u32.u64 %0, t; }"
        : "=r"(a) : "l"(p));
    return a;
}
__device__ __forceinline__ void ldsm4(uint32_t* r, uint32_t addr) {
    asm volatile("ldmatrix.sync.aligned.m8n8.x4.shared.b16 {%0,%1,%2,%3}, [%4];"
        : "=r"(r[0]), "=r"(r[1]), "=r"(r[2]), "=r"(r[3]) : "r"(addr));
}
__device__ __forceinline__ void ldsm4t(uint32_t* r, uint32_t addr) {
    asm volatile("ldmatrix.sync.aligned.m8n8.x4.trans.shared.b16 {%0,%1,%2,%3}, [%4];"
        : "=r"(r[0]), "=r"(r[1]), "=r"(r[2]), "=r"(r[3]) : "r"(addr));
}
__device__ __forceinline__ void mma16816(float* d, const uint32_t* a,
                                         uint32_t b0, uint32_t b1) {
    asm("mma.sync.aligned.m16n8k16.row.col.f32.f16.f16.f32 "
        "{%0,%1,%2,%3}, {%4,%5,%6,%7}, {%8,%9}, {%0,%1,%2,%3};"
        : "+f"(d[0]), "+f"(d[1]), "+f"(d[2]), "+f"(d[3])
        : "r"(a[0]), "r"(a[1]), "r"(a[2]), "r"(a[3]), "r"(b0), "r"(b1));
}
__device__ __forceinline__ float lo_of(float v) {
    return v - __half2float(__float2half(v));
}

// ---------------------------------------------------------------------------
// Kernel 0: weight conversion -> [192][1024] K-major fp16.
// grid = (16, 3), block = 256. smem transpose: coalesced reads AND writes.
// ---------------------------------------------------------------------------
__global__ void conv_w_kernel(const float* __restrict__ Wq,
                              const float* __restrict__ Wk,
                              const float* __restrict__ Wv)
{
    __shared__ float tile[64][65];
    const int kb  = blockIdx.x * 64;
    const int mat = blockIdx.y;
    const int tid = threadIdx.x;
    const float* W = (mat == 0) ? Wq : (mat == 1) ? Wk : Wv;

#pragma unroll
    for (int i = tid; i < 4096; i += 256) {
        int k = i >> 6, n = i & 63;
        tile[k][n] = W[(size_t)(kb + k) * 64 + n];
    }
    __syncthreads();
#pragma unroll
    for (int i = tid; i < 4096; i += 256) {
        int n = i >> 6, k = i & 63;
        g_Bh[(size_t)(mat * 64 + n) * 1024 + kb + k] = __float2half(tile[k][n]);
    }
}

// ---------------------------------------------------------------------------
// Kernel 1: QKV projection via mma.sync fp16 single product.
// grid = 128 (M tiles of 128), block = 256 (2x4 warp grid, 64Mx48N each).
// D[128x192] = Xh*Wh, K=1024 in BK=64 chunks, double-buffered.
// ---------------------------------------------------------------------------
#define QSTR 144                   // smem row stride bytes (72 fp16)
#define XH_OFF 0                   // elem offsets within one buffer
#define WH_OFF 9216                // 128*72
#define QBUF_ELEMS 23040           // 9216 + 192*72
#define QKV_SMEM_BYTES (2 * QBUF_ELEMS * 2)   // 92160

__global__ __launch_bounds__(256) void qkv_tc_kernel(const float* __restrict__ x)
{
    extern __shared__ __half qs[];
    const uint32_t uBase = smem_u32(qs);

    const int tid  = threadIdx.x;
    const int wid  = tid >> 5;
    const int lane = tid & 31;
    const int wm   = wid >> 2;       // 0..1 (M half)
    const int wn   = wid & 3;        // 0..3 (N quarter: 48 cols)
    const int m4   = lane >> 3;
    const int r8   = lane & 7;
    const int g    = lane >> 2;
    const int tg   = lane & 3;
    const int row0 = blockIdx.x * 128;

    // staging mapping
    const int xr  = tid >> 1;          // x row 0..127
    const int xc0 = (tid & 1) * 32;    // 32-elem half

    float acc[4][6][4] = {};
    float4 xv[8];
    uint4  wh6[6];

#define LOADX(c) do { \
    _Pragma("unroll") \
    for (int j = 0; j < 8; j++) \
        xv[j] = *(const float4*)&x[(size_t)(row0 + xr) * EMB + (c) * 64 + xc0 + j * 4]; \
    _Pragma("unroll") \
    for (int j = 0; j < 6; j++) { \
        int gi = tid + j * 256; \
        int rw = gi >> 3, sg = gi & 7; \
        wh6[j] = *(const uint4*)&g_Bh[rw * 1024 + (c) * 64 + sg * 8]; \
    } \
} while (0)

#define STOREB(b) do { \
    __half* base = qs + (b) * QBUF_ELEMS; \
    _Pragma("unroll") \
    for (int j = 0; j < 8; j++) { \
        uint32_t h0 = pkh(xv[j].y, xv[j].x); \
        uint32_t h1 = pkh(xv[j].w, xv[j].z); \
        *(uint2*)(base + XH_OFF + xr * 72 + xc0 + j * 4) = make_uint2(h0, h1); \
    } \
    _Pragma("unroll") \
    for (int j = 0; j < 6; j++) { \
        int gi = tid + j * 256; \
        int rw = gi >> 3, sg = gi & 7; \
        *(uint4*)(base + WH_OFF + rw * 72 + sg * 8) = wh6[j]; \
    } \
} while (0)

    // prologue
    LOADX(0);
    STOREB(0);

    for (int c = 0; c < 16; c++) {
        const int cur = c & 1;
        if (c < 15) LOADX(c + 1);
        __syncthreads();
        if (c < 15) STOREB(cur ^ 1);

        const uint32_t uB  = uBase + cur * (QBUF_ELEMS * 2);
        const uint32_t uXh = uB + XH_OFF * 2;
        const uint32_t uWh = uB + WH_OFF * 2;

#pragma unroll
        for (int kcb = 0; kcb < 4; kcb += 2) {
            uint32_t ah[4][2][4];
#pragma unroll
            for (int mf = 0; mf < 4; mf++)
#pragma unroll
                for (int kk = 0; kk < 2; kk++) {
                    uint32_t off = (uint32_t)((wm * 64 + mf * 16 + (m4 & 1) * 8 + r8) * QSTR
                                   + ((kcb + kk) * 16 + (m4 >> 1) * 8) * 2);
                    ldsm4(ah[mf][kk], uXh + off);
                }
#pragma unroll
            for (int nf = 0; nf < 6; nf++) {
                uint32_t bh[4];
                uint32_t off = (uint32_t)((wn * 48 + nf * 8 + r8) * QSTR
                               + (kcb * 16 + (m4 & 1) * 8 + (m4 >> 1) * 16) * 2);
                ldsm4(bh, uWh + off);
#pragma unroll
                for (int mf = 0; mf < 4; mf++) {
                    mma16816(acc[mf][nf], ah[mf][0], bh[0], bh[1]);
                    mma16816(acc[mf][nf], ah[mf][1], bh[2], bh[3]);
                }
            }
        }
    }

    // epilogue: q -> fp16 (scaled); k,v -> fp16 hi/lo
#pragma unroll
    for (int mf = 0; mf < 4; mf++) {
        const int r0 = row0 + wm * 64 + mf * 16 + g;
#pragma unroll
        for (int nf = 0; nf < 6; nf++) {
            const int n   = wn * 48 + nf * 8 + 2 * tg;
            const int mat = n >> 6;
            const int lc  = n & 63;
            float v0 = acc[mf][nf][0], v1 = acc[mf][nf][1];
            float v2 = acc[mf][nf][2], v3 = acc[mf][nf][3];
            if (mat == 0) {
                v0 *= SCALE; v1 *= SCALE; v2 *= SCALE; v3 *= SCALE;
                *(uint32_t*)&g_q[(size_t)r0 * 64 + lc]       = pkh(v1, v0);
                *(uint32_t*)&g_q[(size_t)(r0 + 8) * 64 + lc] = pkh(v3, v2);
            } else {
                __half* oh = (mat == 1) ? g_kh : g_vh;
                __half* ol = (mat == 1) ? g_kl : g_vl;
                *(uint32_t*)&oh[(size_t)r0 * 64 + lc]       = pkh(v1, v0);
                *(uint32_t*)&ol[(size_t)r0 * 64 + lc]       = pkh(lo_of(v1), lo_of(v0));
                *(uint32_t*)&oh[(size_t)(r0 + 8) * 64 + lc] = pkh(v3, v2);
                *(uint32_t*)&ol[(size_t)(r0 + 8) * 64 + lc] = pkh(lo_of(v3), lo_of(v2));
            }
        }
    }
#undef LOADX
#undef STOREB
}

// ---------------------------------------------------------------------------
// Kernel 2: causal flash attention on mma.sync fp16 2-product split.
// Load-balanced: each CTA processes q-tiles (31-pair) and (pair) => 33 steps.
// 128 threads (4 warps x 16 q-rows). grid = 128 (batch x 16 pairs).
// ---------------------------------------------------------------------------
#define SROW 72                       // smem row stride in fp16 elems
#define ATTN_SMEM_BYTES (5 * 64 * SROW * 2)   // Kh,Kl,Vh,Vl,Q = 46080

__global__ __launch_bounds__(128) void attn_kernel(float* __restrict__ out)
{
    extern __shared__ __half smh[];
    __half* sKh = smh;
    __half* sKl = smh + 64 * SROW;
    __half* sVh = smh + 2 * 64 * SROW;
    __half* sVl = smh + 3 * 64 * SROW;
    __half* sQ  = smh + 4 * 64 * SROW;

    const uint32_t uKh = smem_u32(sKh);
    const uint32_t uKl = smem_u32(sKl);
    const uint32_t uVh = smem_u32(sVh);
    const uint32_t uVl = smem_u32(sVl);
    const uint32_t uQ  = smem_u32(sQ);

    const int bid   = blockIdx.x;
    const int batch = bid & 7;
    const int pair  = bid >> 3;         // 0..15

    const int tid  = threadIdx.x;
    const int wq   = tid >> 5;          // warp 0..3, q rows wq*16..+15
    const int lane = tid & 31;
    const int g    = lane >> 2;         // 0..7
    const int tg   = lane & 3;          // 0..3
    const int m4   = lane >> 3;         // ldmatrix matrix id 0..3
    const int r8   = lane & 7;

    const size_t bb = (size_t)batch * SEQ * HD;
    const __half* gq  = g_q  + bb;
    const __half* gkh = g_kh + bb;
    const __half* gkl = g_kl + bb;
    const __half* gvh = g_vh + bb;
    const __half* gvl = g_vl + bb;
    float* ob = out + bb;

    // staging mapping: thread -> (row, 32-elem half-row)
    const int srow = tid >> 1;
    const int scol = (tid & 1) * 32;

    for (int t = 0; t < 2; t++) {
        const int qt = t ? pair : (31 - pair);
        const int q0 = qt * 64;

        // ---- stage Q, build Q fragments ----
        __syncthreads();   // sQ safe to overwrite (t=1); harmless at t=0
        {
            const uint4* sq = (const uint4*)(gq + (size_t)(q0 + srow) * HD + scol);
            uint4 tq[4];
#pragma unroll
            for (int j = 0; j < 4; j++) tq[j] = sq[j];
#pragma unroll
            for (int j = 0; j < 4; j++)
                *(uint4*)(sQ + srow * SROW + scol + 8 * j) = tq[j];
        }
        __syncthreads();

        uint32_t qh[4][4];
        {
            const int qrow = wq * 16 + ((m4 & 1) << 3) + r8;
#pragma unroll
            for (int kc = 0; kc < 4; kc++) {
                uint32_t off = (uint32_t)(qrow * (SROW * 2) + (kc * 16 + (m4 >> 1) * 8) * 2);
                ldsm4(qh[kc], uQ + off);
            }
        }

        float o[8][4] = {};
        float m0 = -1e30f, m1 = -1e30f;
        float l0 = 0.f, l1 = 0.f;
        const int qrow0 = q0 + wq * 16 + g;
        const int qrow1 = qrow0 + 8;

        for (int kt = 0; kt <= qt; kt++) {
            const int k0 = kt * 64;

            // ---- stage K/V (prefetch into regs, 2 syncs) ----
            uint4 pf[16];
            {
                const uint4* s0 = (const uint4*)(gkh + (size_t)(k0 + srow) * HD + scol);
                const uint4* s1 = (const uint4*)(gkl + (size_t)(k0 + srow) * HD + scol);
                const uint4* s2 = (const uint4*)(gvh + (size_t)(k0 + srow) * HD + scol);
                const uint4* s3 = (const uint4*)(gvl + (size_t)(k0 + srow) * HD + scol);
#pragma unroll
                for (int j = 0; j < 4; j++) {
                    pf[j]      = s0[j];
                    pf[4 + j]  = s1[j];
                    pf[8 + j]  = s2[j];
                    pf[12 + j] = s3[j];
                }
            }
            __syncthreads();   // prior LDSM reads done
#pragma unroll
            for (int j = 0; j < 4; j++) {
                *(uint4*)(sKh + srow * SROW + scol + 8 * j) = pf[j];
                *(uint4*)(sKl + srow * SROW + scol + 8 * j) = pf[4 + j];
                *(uint4*)(sVh + srow * SROW + scol + 8 * j) = pf[8 + j];
                *(uint4*)(sVl + srow * SROW + scol + 8 * j) = pf[12 + j];
            }
            __syncthreads();   // tiles visible

            // ---- S = Q K^T  (fp16 split: q·Kh + q·Kl) ----
            float sf[8][4];
#pragma unroll
            for (int nf = 0; nf < 8; nf++) {
                sf[nf][0] = sf[nf][1] = sf[nf][2] = sf[nf][3] = 0.f;
#pragma unroll
                for (int kcb = 0; kcb < 4; kcb += 2) {
                    uint32_t bh[4], bl[4];
                    uint32_t off = (uint32_t)((nf * 8 + r8) * (SROW * 2) +
                                   (kcb * 16 + (m4 & 1) * 8 + (m4 >> 1) * 16) * 2);
                    ldsm4(bh, uKh + off);
                    ldsm4(bl, uKl + off);
                    mma16816(sf[nf], qh[kcb],     bh[0], bh[1]);
                    mma16816(sf[nf], qh[kcb],     bl[0], bl[1]);
                    mma16816(sf[nf], qh[kcb + 1], bh[2], bh[3]);
                    mma16816(sf[nf], qh[kcb + 1], bl[2], bl[3]);
                }
            }

            // ---- causal mask (diagonal tile) ----
            if (kt == qt) {
#pragma unroll
                for (int nf = 0; nf < 8; nf++) {
                    const int col = k0 + nf * 8 + 2 * tg;
                    if (col     > qrow0) sf[nf][0] = -1e30f;
                    if (col + 1 > qrow0) sf[nf][1] = -1e30f;
                    if (col     > qrow1) sf[nf][2] = -1e30f;
                    if (col + 1 > qrow1) sf[nf][3] = -1e30f;
                }
            }

            // ---- online softmax (rows g, g+8; 4-lane shfl groups) ----
            float mx0 = -1e30f, mx1 = -1e30f;
#pragma unroll
            for (int nf = 0; nf < 8; nf++) {
                mx0 = fmaxf(mx0, fmaxf(sf[nf][0], sf[nf][1]));
                mx1 = fmaxf(mx1, fmaxf(sf[nf][2], sf[nf][3]));
            }
            mx0 = fmaxf(mx0, __shfl_xor_sync(0xffffffffu, mx0, 1));
            mx0 = fmaxf(mx0, __shfl_xor_sync(0xffffffffu, mx0, 2));
            mx1 = fmaxf(mx1, __shfl_xor_sync(0xffffffffu, mx1, 1));
            mx1 = fmaxf(mx1, __shfl_xor_sync(0xffffffffu, mx1, 2));

            const float mn0 = fmaxf(m0, mx0);
            const float mn1 = fmaxf(m1, mx1);
            const float c0 = __expf(m0 - mn0);
            const float c1 = __expf(m1 - mn1);
            m0 = mn0; m1 = mn1;

            float sum0 = 0.f, sum1 = 0.f;
#pragma unroll
            for (int nf = 0; nf < 8; nf++) {
                sf[nf][0] = __expf(sf[nf][0] - mn0);
                sf[nf][1] = __expf(sf[nf][1] - mn0);
                sf[nf][2] = __expf(sf[nf][2] - mn1);
                sf[nf][3] = __expf(sf[nf][3] - mn1);
                sum0 += sf[nf][0] + sf[nf][1];
                sum1 += sf[nf][2] + sf[nf][3];
            }
            sum0 += __shfl_xor_sync(0xffffffffu, sum0, 1);
            sum0 += __shfl_xor_sync(0xffffffffu, sum0, 2);
            sum1 += __shfl_xor_sync(0xffffffffu, sum1, 1);
            sum1 += __shfl_xor_sync(0xffffffffu, sum1, 2);
            l0 = l0 * c0 + sum0;
            l1 = l1 * c1 + sum1;

#pragma unroll
            for (int nf = 0; nf < 8; nf++) {
                o[nf][0] *= c0; o[nf][1] *= c0;
                o[nf][2] *= c1; o[nf][3] *= c1;
            }

            // ---- P -> fp16 A-fragments ----
            uint32_t ph[4][4];
#pragma unroll
            for (int kc = 0; kc < 4; kc++) {
                const int f0 = 2 * kc, f1 = 2 * kc + 1;
                ph[kc][0] = pkh(sf[f0][1], sf[f0][0]);
                ph[kc][1] = pkh(sf[f0][3], sf[f0][2]);
                ph[kc][2] = pkh(sf[f1][1], sf[f1][0]);
                ph[kc][3] = pkh(sf[f1][3], sf[f1][2]);
            }

            // ---- O += P V  (P·Vh + P·Vl), V via ldmatrix.trans ----
#pragma unroll
            for (int nf = 0; nf < 8; nf++) {
#pragma unroll
                for (int kcb = 0; kcb < 4; kcb += 2) {
                    uint32_t bh[4], bl[4];
                    uint32_t off = (uint32_t)((kcb * 16 + (m4 & 1) * 8 + (m4 >> 1) * 16 + r8)
                                   * (SROW * 2) + nf * 16);
                    ldsm4t(bh, uVh + off);
                    ldsm4t(bl, uVl + off);
                    mma16816(o[nf], ph[kcb],     bh[0], bh[1]);
                    mma16816(o[nf], ph[kcb],     bl[0], bl[1]);
                    mma16816(o[nf], ph[kcb + 1], bh[2], bh[3]);
                    mma16816(o[nf], ph[kcb + 1], bl[2], bl[3]);
                }
            }
        }

        // ---- epilogue for this q-tile ----
        const float inv0 = 1.f / l0;
        const float inv1 = 1.f / l1;
#pragma unroll
        for (int nf = 0; nf < 8; nf++) {
            *(float2*)&ob[(size_t)qrow0 * HD + nf * 8 + 2 * tg] =
                make_float2(o[nf][0] * inv0, o[nf][1] * inv0);
            *(float2*)&ob[(size_t)qrow1 * HD + nf * 8 + 2 * tg] =
                make_float2(o[nf][2] * inv1, o[nf][3] * inv1);
        }
    }
}

// ---------------------------------------------------------------------------
extern "C" void kernel_launch(void* const* d_in, const int* in_sizes, int n_in,
                              void* d_out, int out_size)
{
    const float* x  = (const float*)d_in[0];
    const float* Wq = (const float*)d_in[1];
    const float* Wk = (const float*)d_in[2];
    const float* Wv = (const float*)d_in[3];
    float* out = (float*)d_out;

    static bool attr_set = false;
    if (!attr_set) {
        cudaFuncSetAttribute(attn_kernel,
                             cudaFuncAttributeMaxDynamicSharedMemorySize,
                             ATTN_SMEM_BYTES);
        cudaFuncSetAttribute(qkv_tc_kernel,
                             cudaFuncAttributeMaxDynamicSharedMemorySize,
                             QKV_SMEM_BYTES);
        attr_set = true;
    }

    conv_w_kernel<<<dim3(16, 3), 256>>>(Wq, Wk, Wv);
    qkv_tc_kernel<<<MROWS / 128, 256, QKV_SMEM_BYTES>>>(x);
    attn_kernel<<<BATCH * 16, 128, ATTN_SMEM_BYTES>>>(out);
}